// round 1
// baseline (speedup 1.0000x reference)
#include <cuda_runtime.h>
#include <math.h>

// Problem constants (fixed by setup_inputs)
#define B_   4
#define N_   1024
#define C_   1024
#define H_   16
#define D_   64
#define NC_  256
#define M_   1280            // NC_ + N_
#define KTILES 20            // M_/64

// Scratch (allocation-free rule: __device__ globals)
__device__ float g_qkv[(size_t)B_ * N_ * 3 * C_];   // (B,N,3,H,D) = (B,N,3C)
__device__ float g_attn[(size_t)B_ * N_ * C_];      // (B,N,H,D) = (B,N,C)

// ---------------------------------------------------------------------------
// NT GEMM: C[M,N] = A[M,K] @ B[N,K]^T (+ bias). 128x128x8 tile, 256 thr, 8x8/thr
// ---------------------------------------------------------------------------
template <bool BIAS>
__global__ __launch_bounds__(256) void gemm_nt(
    const float* __restrict__ A, const float* __restrict__ Bm,
    const float* __restrict__ bias, float* __restrict__ C,
    int M, int N, int K)
{
    __shared__ float As[8][132];
    __shared__ float Bs[8][132];

    const int tid = threadIdx.x;
    const int bm = blockIdx.y * 128;
    const int bn = blockIdx.x * 128;

    const int lr = tid >> 1;          // 0..127 (row within tile to load)
    const int lk = (tid & 1) << 2;    // 0 or 4 (k offset)
    const float* Ap = A + (size_t)(bm + lr) * K + lk;
    const float* Bp = Bm + (size_t)(bn + lr) * K + lk;

    const int tr = (tid >> 4) << 3;   // 0..120
    const int tc = (tid & 15) << 3;   // 0..120

    float acc[8][8];
#pragma unroll
    for (int i = 0; i < 8; i++)
#pragma unroll
        for (int j = 0; j < 8; j++) acc[i][j] = 0.0f;

    for (int k0 = 0; k0 < K; k0 += 8) {
        float4 av = *(const float4*)(Ap + k0);
        float4 bv = *(const float4*)(Bp + k0);
        As[lk + 0][lr] = av.x; As[lk + 1][lr] = av.y;
        As[lk + 2][lr] = av.z; As[lk + 3][lr] = av.w;
        Bs[lk + 0][lr] = bv.x; Bs[lk + 1][lr] = bv.y;
        Bs[lk + 2][lr] = bv.z; Bs[lk + 3][lr] = bv.w;
        __syncthreads();

#pragma unroll
        for (int kk = 0; kk < 8; kk++) {
            float ar[8], br[8];
#pragma unroll
            for (int i = 0; i < 8; i++) ar[i] = As[kk][tr + i];
#pragma unroll
            for (int j = 0; j < 8; j++) br[j] = Bs[kk][tc + j];
#pragma unroll
            for (int i = 0; i < 8; i++)
#pragma unroll
                for (int j = 0; j < 8; j++)
                    acc[i][j] = fmaf(ar[i], br[j], acc[i][j]);
        }
        __syncthreads();
    }

#pragma unroll
    for (int i = 0; i < 8; i++) {
        float* Cp = C + (size_t)(bm + tr + i) * N + bn + tc;
#pragma unroll
        for (int j = 0; j < 8; j++) {
            float v = acc[i][j];
            if (BIAS) v += bias[bn + tc + j];
            Cp[j] = v;
        }
    }
}

// ---------------------------------------------------------------------------
// Flash attention: block = (64-query tile, head, batch). 256 threads.
// Thread (ty,tx) in 16x16 grid owns 4 query rows x 4 (keys | dims).
// smem: Q,K,V,P tiles each 64x68 floats -> 69632 B dynamic smem.
// ---------------------------------------------------------------------------
#define SMEM_ATTN (4 * 64 * 68 * 4)

__global__ __launch_bounds__(256) void attn_kernel(
    const float* __restrict__ qkv, const float* __restrict__ ctx,
    float* __restrict__ out)
{
    extern __shared__ float sm[];
    float* Qs = sm;                 // [64][68]
    float* Ks = Qs + 64 * 68;
    float* Vs = Ks + 64 * 68;
    float* Ps = Vs + 64 * 68;

    const int tid = threadIdx.x;
    const int qt = blockIdx.x;      // 0..15
    const int h  = blockIdx.y;      // 0..15
    const int b  = blockIdx.z;      // 0..3
    const int ty = tid >> 4;        // 0..15
    const int tx = tid & 15;        // 0..15
    const int ty4 = ty << 2;
    const int tx4 = tx << 2;
    const int n0 = qt * 64;
    const float scale = 0.125f;     // D^-0.5

    // Load Q tile (scaled). 64 rows x 16 float4 = 1024 float4, 4 per thread.
#pragma unroll
    for (int it = 0; it < 4; it++) {
        int idx = tid + it * 256;
        int r = idx >> 4;
        int c = (idx & 15) << 2;
        const float* p = qkv + ((size_t)(b * N_ + n0 + r) * 3 + 0) * C_ + h * D_ + c;
        float4 v = *(const float4*)p;
        float* q = Qs + r * 68 + c;
        q[0] = v.x * scale; q[1] = v.y * scale;
        q[2] = v.z * scale; q[3] = v.w * scale;
    }

    float m_[4], l_[4], O[4][4];
#pragma unroll
    for (int i = 0; i < 4; i++) {
        m_[i] = -1e30f; l_[i] = 0.0f;
#pragma unroll
        for (int k = 0; k < 4; k++) O[i][k] = 0.0f;
    }

    for (int kt = 0; kt < KTILES; kt++) {
        __syncthreads();   // protect Ks/Vs/Ps from prior iteration readers

        // Load K,V tiles
        const int kbase = kt * 64;
#pragma unroll
        for (int it = 0; it < 4; it++) {
            int idx = tid + it * 256;
            int r = idx >> 4;
            int c = (idx & 15) << 2;
            int mrow = kbase + r;
            const float *pk, *pv;
            if (mrow < NC_) {
                const float* base = ctx + ((size_t)(b * NC_ + mrow) * 2 + 0) * C_ + h * D_ + c;
                pk = base; pv = base + C_;
            } else {
                int mq = mrow - NC_;
                const float* base = qkv + ((size_t)(b * N_ + mq) * 3 + 1) * C_ + h * D_ + c;
                pk = base; pv = base + C_;
            }
            *(float4*)(Ks + r * 68 + c) = *(const float4*)pk;
            *(float4*)(Vs + r * 68 + c) = *(const float4*)pv;
        }
        __syncthreads();

        // S[4][4] = Q_tile(rows ty4..) . K_tile(rows tx4..)^T
        float S[4][4];
#pragma unroll
        for (int i = 0; i < 4; i++)
#pragma unroll
            for (int j = 0; j < 4; j++) S[i][j] = 0.0f;

#pragma unroll 8
        for (int d = 0; d < 64; d++) {
            float a0 = Qs[(ty4 + 0) * 68 + d];
            float a1 = Qs[(ty4 + 1) * 68 + d];
            float a2 = Qs[(ty4 + 2) * 68 + d];
            float a3 = Qs[(ty4 + 3) * 68 + d];
            float b0 = Ks[(tx4 + 0) * 68 + d];
            float b1 = Ks[(tx4 + 1) * 68 + d];
            float b2 = Ks[(tx4 + 2) * 68 + d];
            float b3 = Ks[(tx4 + 3) * 68 + d];
            S[0][0] = fmaf(a0, b0, S[0][0]); S[0][1] = fmaf(a0, b1, S[0][1]);
            S[0][2] = fmaf(a0, b2, S[0][2]); S[0][3] = fmaf(a0, b3, S[0][3]);
            S[1][0] = fmaf(a1, b0, S[1][0]); S[1][1] = fmaf(a1, b1, S[1][1]);
            S[1][2] = fmaf(a1, b2, S[1][2]); S[1][3] = fmaf(a1, b3, S[1][3]);
            S[2][0] = fmaf(a2, b0, S[2][0]); S[2][1] = fmaf(a2, b1, S[2][1]);
            S[2][2] = fmaf(a2, b2, S[2][2]); S[2][3] = fmaf(a2, b3, S[2][3]);
            S[3][0] = fmaf(a3, b0, S[3][0]); S[3][1] = fmaf(a3, b1, S[3][1]);
            S[3][2] = fmaf(a3, b2, S[3][2]); S[3][3] = fmaf(a3, b3, S[3][3]);
        }

        // Online softmax. Row-group = 16 threads (half-warp, lanes differ in bits 0..3).
        float mt[4];
#pragma unroll
        for (int i = 0; i < 4; i++)
            mt[i] = fmaxf(fmaxf(S[i][0], S[i][1]), fmaxf(S[i][2], S[i][3]));
#pragma unroll
        for (int off = 1; off < 16; off <<= 1)
#pragma unroll
            for (int i = 0; i < 4; i++)
                mt[i] = fmaxf(mt[i], __shfl_xor_sync(0xffffffffu, mt[i], off));

        float alpha[4];
#pragma unroll
        for (int i = 0; i < 4; i++) {
            float mn = fmaxf(m_[i], mt[i]);
            alpha[i] = __expf(m_[i] - mn);
            m_[i] = mn;
        }

        float ps[4] = {0.f, 0.f, 0.f, 0.f};
#pragma unroll
        for (int i = 0; i < 4; i++)
#pragma unroll
            for (int j = 0; j < 4; j++) {
                float p = __expf(S[i][j] - m_[i]);
                Ps[(ty4 + i) * 68 + tx4 + j] = p;
                ps[i] += p;
            }
#pragma unroll
        for (int off = 1; off < 16; off <<= 1)
#pragma unroll
            for (int i = 0; i < 4; i++)
                ps[i] += __shfl_xor_sync(0xffffffffu, ps[i], off);

#pragma unroll
        for (int i = 0; i < 4; i++) {
            l_[i] = l_[i] * alpha[i] + ps[i];
#pragma unroll
            for (int k = 0; k < 4; k++) O[i][k] *= alpha[i];
        }
        __syncthreads();   // Ps visible to everyone

        // O[4 rows][4 dims] += P(rows ty4..) . V(dims tx4..)
#pragma unroll 8
        for (int j = 0; j < 64; j++) {
            const float4 vv = *(const float4*)(Vs + j * 68 + tx4);
            float p0 = Ps[(ty4 + 0) * 68 + j];
            float p1 = Ps[(ty4 + 1) * 68 + j];
            float p2 = Ps[(ty4 + 2) * 68 + j];
            float p3 = Ps[(ty4 + 3) * 68 + j];
            O[0][0] = fmaf(p0, vv.x, O[0][0]); O[0][1] = fmaf(p0, vv.y, O[0][1]);
            O[0][2] = fmaf(p0, vv.z, O[0][2]); O[0][3] = fmaf(p0, vv.w, O[0][3]);
            O[1][0] = fmaf(p1, vv.x, O[1][0]); O[1][1] = fmaf(p1, vv.y, O[1][1]);
            O[1][2] = fmaf(p1, vv.z, O[1][2]); O[1][3] = fmaf(p1, vv.w, O[1][3]);
            O[2][0] = fmaf(p2, vv.x, O[2][0]); O[2][1] = fmaf(p2, vv.y, O[2][1]);
            O[2][2] = fmaf(p2, vv.z, O[2][2]); O[2][3] = fmaf(p2, vv.w, O[2][3]);
            O[3][0] = fmaf(p3, vv.x, O[3][0]); O[3][1] = fmaf(p3, vv.y, O[3][1]);
            O[3][2] = fmaf(p3, vv.z, O[3][2]); O[3][3] = fmaf(p3, vv.w, O[3][3]);
        }
    }

    // Epilogue: O/l -> g_attn laid out (B,N,H,D)=(B,N,C)
#pragma unroll
    for (int i = 0; i < 4; i++) {
        float inv = 1.0f / l_[i];
        float4 v;
        v.x = O[i][0] * inv; v.y = O[i][1] * inv;
        v.z = O[i][2] * inv; v.w = O[i][3] * inv;
        float* op = out + (size_t)(b * N_ + n0 + ty4 + i) * C_ + h * D_ + tx4;
        *(float4*)op = v;
    }
}

// ---------------------------------------------------------------------------
extern "C" void kernel_launch(void* const* d_in, const int* in_sizes, int n_in,
                              void* d_out, int out_size) {
    const float* x      = (const float*)d_in[0];  // (B,N,C)
    const float* ctx    = (const float*)d_in[1];  // (B,NC,2C)
    const float* w_qkv  = (const float*)d_in[2];  // (3C,C)
    const float* w_proj = (const float*)d_in[3];  // (C,C)
    const float* b_proj = (const float*)d_in[4];  // (C,)
    float* out = (float*)d_out;                   // (B,N,C)

    void *qkvp_v, *attnp_v;
    cudaGetSymbolAddress(&qkvp_v, g_qkv);
    cudaGetSymbolAddress(&attnp_v, g_attn);
    float* qkvp  = (float*)qkvp_v;
    float* attnp = (float*)attnp_v;

    // 1) QKV projection: (4096,3072) = x(4096,1024) @ w_qkv^T
    {
        dim3 grid(3 * C_ / 128, B_ * N_ / 128);
        gemm_nt<false><<<grid, 256>>>(x, w_qkv, nullptr, qkvp,
                                      B_ * N_, 3 * C_, C_);
    }

    // 2) Attention
    {
        cudaFuncSetAttribute(attn_kernel,
                             cudaFuncAttributeMaxDynamicSharedMemorySize,
                             SMEM_ATTN);
        dim3 grid(N_ / 64, H_, B_);
        attn_kernel<<<grid, 256, SMEM_ATTN>>>(qkvp, ctx, attnp);
    }

    // 3) Output projection with bias
    {
        dim3 grid(C_ / 128, B_ * N_ / 128);
        gemm_nt<true><<<grid, 256>>>(attnp, w_proj, b_proj, out,
                                     B_ * N_, C_, C_);
    }
}

// round 3
// speedup vs baseline: 1.4814x; 1.4814x over previous
#include <cuda_runtime.h>
#include <cuda_bf16.h>
#include <cstdint>
#include <math.h>

// Problem constants (fixed by setup_inputs)
#define B_   4
#define N_   1024
#define C_   1024
#define H_   16
#define D_   64
#define NC_  256
#define M_   1280            // NC_ + N_
#define KTILES 20            // M_/64

// ---------------------------------------------------------------------------
// Scratch (allocation-free rule: __device__ globals)
// ---------------------------------------------------------------------------
__device__ float        g_qkv[(size_t)B_ * N_ * 3 * C_];     // fp32 (B,N,3C)
__device__ __nv_bfloat16 g_xhi[(size_t)B_ * N_ * C_];
__device__ __nv_bfloat16 g_xlo[(size_t)B_ * N_ * C_];
__device__ __nv_bfloat16 g_wqkv_hi[(size_t)3 * C_ * C_];
__device__ __nv_bfloat16 g_wqkv_lo[(size_t)3 * C_ * C_];
__device__ __nv_bfloat16 g_wproj_hi[(size_t)C_ * C_];
__device__ __nv_bfloat16 g_wproj_lo[(size_t)C_ * C_];
__device__ __nv_bfloat16 g_ahi[(size_t)B_ * N_ * C_];        // attention out hi
__device__ __nv_bfloat16 g_alo[(size_t)B_ * N_ * C_];        // attention out lo

// ---------------------------------------------------------------------------
// Helpers (sm_100 baseline PTX only — NO 'a'-gated features)
// ---------------------------------------------------------------------------
__device__ __forceinline__ uint32_t smem_u32(const void* p) {
    uint32_t a;
    asm("{ .reg .u64 t; cvta.to.shared.u64 t, %1; cvt.u32.u64 %0, t; }" : "=r"(a) : "l"(p));
    return a;
}
__device__ __forceinline__ void cpa16(uint32_t d, const void* g) {
    asm volatile("cp.async.cg.shared.global [%0], [%1], 16;" :: "r"(d), "l"(g));
}
__device__ __forceinline__ void cpa_commit() { asm volatile("cp.async.commit_group;"); }
template <int n> __device__ __forceinline__ void cpa_wait() {
    asm volatile("cp.async.wait_group %0;" :: "n"(n));
}
__device__ __forceinline__ uint32_t sw128(uint32_t off) { return off ^ ((off >> 3) & 0x70); }

__device__ __forceinline__ void ldsm_x4(uint32_t* r, uint32_t addr) {
    asm volatile("ldmatrix.sync.aligned.m8n8.x4.shared.b16 {%0,%1,%2,%3}, [%4];"
        : "=r"(r[0]), "=r"(r[1]), "=r"(r[2]), "=r"(r[3]) : "r"(addr));
}
__device__ __forceinline__ void mma_bf16(float* d, const uint32_t* a,
                                         uint32_t b0, uint32_t b1) {
    asm volatile(
        "mma.sync.aligned.m16n8k16.row.col.f32.bf16.bf16.f32 "
        "{%0,%1,%2,%3},{%4,%5,%6,%7},{%8,%9},{%0,%1,%2,%3};"
        : "+f"(d[0]), "+f"(d[1]), "+f"(d[2]), "+f"(d[3])
        : "r"(a[0]), "r"(a[1]), "r"(a[2]), "r"(a[3]), "r"(b0), "r"(b1));
}

// ---------------------------------------------------------------------------
// fp32 -> bf16 hi/lo decomposition (vectorized float4)
// ---------------------------------------------------------------------------
__global__ void decomp_kernel(const float* __restrict__ in,
                              __nv_bfloat16* __restrict__ hi,
                              __nv_bfloat16* __restrict__ lo, int n4) {
    int i = blockIdx.x * blockDim.x + threadIdx.x;
    if (i >= n4) return;
    float4 v = ((const float4*)in)[i];
    __nv_bfloat16 h[4], l[4];
    float x[4] = {v.x, v.y, v.z, v.w};
#pragma unroll
    for (int k = 0; k < 4; k++) {
        h[k] = __float2bfloat16(x[k]);
        l[k] = __float2bfloat16(x[k] - __bfloat162float(h[k]));
    }
    ((__nv_bfloat162*)hi)[i * 2 + 0] = __nv_bfloat162(h[0], h[1]);
    ((__nv_bfloat162*)hi)[i * 2 + 1] = __nv_bfloat162(h[2], h[3]);
    ((__nv_bfloat162*)lo)[i * 2 + 0] = __nv_bfloat162(l[0], l[1]);
    ((__nv_bfloat162*)lo)[i * 2 + 1] = __nv_bfloat162(l[2], l[3]);
}

// ---------------------------------------------------------------------------
// mma.sync bf16x3 GEMM: C[M,N] = A[M,K] @ B[N,K]^T (+ bias)
// 128x128 tile, K-chunk 64, 8 warps (2x4), 64x32 per warp, cp.async 2-stage.
// ---------------------------------------------------------------------------
#define GKC 64
#define TILE_B 16384                 // 128 rows x 128 bytes
#define STAGE_BYTES (4 * TILE_B)     // Ahi, Alo, Bhi, Blo
#define GEMM_SMEM (2 * STAGE_BYTES + 1024)

__device__ __forceinline__ void load_tile(const __nv_bfloat16* __restrict__ src,
                                          int rbase, int K, int k0,
                                          uint32_t tb, int tid) {
#pragma unroll
    for (int i = 0; i < 4; i++) {
        int idx = tid + i * 256;
        int r = idx >> 3;
        int c = idx & 7;
        const void* g = src + (size_t)(rbase + r) * K + k0 + c * 8;
        cpa16(tb + sw128((uint32_t)(r * 128 + c * 16)), g);
    }
}

template <bool BIAS>
__global__ __launch_bounds__(256) void gemm_mma(
    const __nv_bfloat16* __restrict__ Ahi, const __nv_bfloat16* __restrict__ Alo,
    const __nv_bfloat16* __restrict__ Bhi, const __nv_bfloat16* __restrict__ Blo,
    const float* __restrict__ bias, float* __restrict__ Cout,
    int M, int N, int K)
{
    extern __shared__ char sm[];
    const uint32_t tiles = (smem_u32(sm) + 1023) & ~1023u;

    const int tid  = threadIdx.x;
    const int lane = tid & 31;
    const int wid  = tid >> 5;
    const int wm0  = (wid >> 2) * 64;   // 0 | 64
    const int wn0  = (wid & 3) * 32;    // 0,32,64,96
    const int bm = blockIdx.y * 128;
    const int bn = blockIdx.x * 128;

    const int lr = lane & 15;           // ldmatrix row within 16-row tile
    const int lc = (lane >> 4) << 4;    // ldmatrix 16B column chunk

    float acc[4][4][4];
#pragma unroll
    for (int i = 0; i < 4; i++)
#pragma unroll
        for (int j = 0; j < 4; j++)
#pragma unroll
            for (int t = 0; t < 4; t++) acc[i][j][t] = 0.0f;

    const int NCH = K / GKC;            // 16

    // preload chunk 0 into stage 0
    {
        uint32_t st = tiles;
        load_tile(Ahi, bm, K, 0, st,              tid);
        load_tile(Alo, bm, K, 0, st + TILE_B,     tid);
        load_tile(Bhi, bn, K, 0, st + 2 * TILE_B, tid);
        load_tile(Blo, bn, K, 0, st + 3 * TILE_B, tid);
        cpa_commit();
    }

    for (int k = 0; k < NCH; k++) {
        const int b = k & 1;
        if (k + 1 < NCH) {
            const int nb = (k + 1) & 1;
            uint32_t st = tiles + nb * STAGE_BYTES;
            const int k0 = (k + 1) * GKC;
            load_tile(Ahi, bm, K, k0, st,              tid);
            load_tile(Alo, bm, K, k0, st + TILE_B,     tid);
            load_tile(Bhi, bn, K, k0, st + 2 * TILE_B, tid);
            load_tile(Blo, bn, K, k0, st + 3 * TILE_B, tid);
            cpa_commit();
            cpa_wait<1>();
        } else {
            cpa_wait<0>();
        }
        __syncthreads();

        const uint32_t st  = tiles + b * STAGE_BYTES;
        const uint32_t tAh = st;
        const uint32_t tAl = st + TILE_B;
        const uint32_t tBh = st + 2 * TILE_B;
        const uint32_t tBl = st + 3 * TILE_B;

#pragma unroll
        for (int kk = 0; kk < 4; kk++) {
            uint32_t ah[4][4], al[4][4], bh[2][4], bl[2][4];
#pragma unroll
            for (int mt = 0; mt < 4; mt++) {
                uint32_t o = sw128((uint32_t)((wm0 + mt * 16 + lr) * 128 + kk * 32 + lc));
                ldsm_x4(ah[mt], tAh + o);
                ldsm_x4(al[mt], tAl + o);
            }
#pragma unroll
            for (int ng = 0; ng < 2; ng++) {
                uint32_t o = sw128((uint32_t)((wn0 + ng * 16 + lr) * 128 + kk * 32 + lc));
                ldsm_x4(bh[ng], tBh + o);
                ldsm_x4(bl[ng], tBl + o);
            }
#pragma unroll
            for (int mt = 0; mt < 4; mt++)
#pragma unroll
                for (int nt = 0; nt < 4; nt++) {
                    const int ng = nt >> 1, s = nt & 1;
                    mma_bf16(acc[mt][nt], ah[mt], bh[ng][s], bh[ng][2 + s]);
                    mma_bf16(acc[mt][nt], ah[mt], bl[ng][s], bl[ng][2 + s]);
                    mma_bf16(acc[mt][nt], al[mt], bh[ng][s], bh[ng][2 + s]);
                }
        }
        __syncthreads();
    }

    // Epilogue: register fragments -> global
    const int gq = lane >> 2;   // 0..7
    const int tg = lane & 3;    // 0..3
#pragma unroll
    for (int mt = 0; mt < 4; mt++) {
        const int row0 = bm + wm0 + mt * 16 + gq;
#pragma unroll
        for (int nt = 0; nt < 4; nt++) {
            const int col = bn + wn0 + nt * 8 + tg * 2;
            float2 v0 = make_float2(acc[mt][nt][0], acc[mt][nt][1]);
            float2 v1 = make_float2(acc[mt][nt][2], acc[mt][nt][3]);
            if (BIAS) {
                float b0v = bias[col], b1v = bias[col + 1];
                v0.x += b0v; v0.y += b1v;
                v1.x += b0v; v1.y += b1v;
            }
            *(float2*)(Cout + (size_t)row0 * N + col)       = v0;
            *(float2*)(Cout + (size_t)(row0 + 8) * N + col) = v1;
        }
    }
}

// ---------------------------------------------------------------------------
// Flash attention (SIMT fp32): block = 64 queries x head x batch. 256 threads.
// Epilogue writes bf16 hi/lo for the mma out-projection.
// ---------------------------------------------------------------------------
#define SMEM_ATTN (4 * 64 * 68 * 4)

__global__ __launch_bounds__(256) void attn_kernel(
    const float* __restrict__ qkv, const float* __restrict__ ctx,
    __nv_bfloat16* __restrict__ ohi, __nv_bfloat16* __restrict__ olo)
{
    extern __shared__ float smf[];
    float* Qs = smf;
    float* Ks = Qs + 64 * 68;
    float* Vs = Ks + 64 * 68;
    float* Ps = Vs + 64 * 68;

    const int tid = threadIdx.x;
    const int qt = blockIdx.x;
    const int h  = blockIdx.y;
    const int b  = blockIdx.z;
    const int ty = tid >> 4;
    const int tx = tid & 15;
    const int ty4 = ty << 2;
    const int tx4 = tx << 2;
    const int n0 = qt * 64;
    const float scale = 0.125f;

#pragma unroll
    for (int it = 0; it < 4; it++) {
        int idx = tid + it * 256;
        int r = idx >> 4;
        int c = (idx & 15) << 2;
        const float* p = qkv + ((size_t)(b * N_ + n0 + r) * 3 + 0) * C_ + h * D_ + c;
        float4 v = *(const float4*)p;
        float* q = Qs + r * 68 + c;
        q[0] = v.x * scale; q[1] = v.y * scale;
        q[2] = v.z * scale; q[3] = v.w * scale;
    }

    float m_[4], l_[4], O[4][4];
#pragma unroll
    for (int i = 0; i < 4; i++) {
        m_[i] = -1e30f; l_[i] = 0.0f;
#pragma unroll
        for (int k = 0; k < 4; k++) O[i][k] = 0.0f;
    }

    for (int kt = 0; kt < KTILES; kt++) {
        __syncthreads();
        const int kbase = kt * 64;
#pragma unroll
        for (int it = 0; it < 4; it++) {
            int idx = tid + it * 256;
            int r = idx >> 4;
            int c = (idx & 15) << 2;
            int mrow = kbase + r;
            const float *pk, *pv;
            if (mrow < NC_) {
                const float* base = ctx + ((size_t)(b * NC_ + mrow) * 2 + 0) * C_ + h * D_ + c;
                pk = base; pv = base + C_;
            } else {
                int mq = mrow - NC_;
                const float* base = qkv + ((size_t)(b * N_ + mq) * 3 + 1) * C_ + h * D_ + c;
                pk = base; pv = base + C_;
            }
            *(float4*)(Ks + r * 68 + c) = *(const float4*)pk;
            *(float4*)(Vs + r * 68 + c) = *(const float4*)pv;
        }
        __syncthreads();

        float S[4][4];
#pragma unroll
        for (int i = 0; i < 4; i++)
#pragma unroll
            for (int j = 0; j < 4; j++) S[i][j] = 0.0f;

#pragma unroll 8
        for (int d = 0; d < 64; d++) {
            float a0 = Qs[(ty4 + 0) * 68 + d];
            float a1 = Qs[(ty4 + 1) * 68 + d];
            float a2 = Qs[(ty4 + 2) * 68 + d];
            float a3 = Qs[(ty4 + 3) * 68 + d];
            float b0 = Ks[(tx4 + 0) * 68 + d];
            float b1 = Ks[(tx4 + 1) * 68 + d];
            float b2 = Ks[(tx4 + 2) * 68 + d];
            float b3 = Ks[(tx4 + 3) * 68 + d];
            S[0][0] = fmaf(a0, b0, S[0][0]); S[0][1] = fmaf(a0, b1, S[0][1]);
            S[0][2] = fmaf(a0, b2, S[0][2]); S[0][3] = fmaf(a0, b3, S[0][3]);
            S[1][0] = fmaf(a1, b0, S[1][0]); S[1][1] = fmaf(a1, b1, S[1][1]);
            S[1][2] = fmaf(a1, b2, S[1][2]); S[1][3] = fmaf(a1, b3, S[1][3]);
            S[2][0] = fmaf(a2, b0, S[2][0]); S[2][1] = fmaf(a2, b1, S[2][1]);
            S[2][2] = fmaf(a2, b2, S[2][2]); S[2][3] = fmaf(a2, b3, S[2][3]);
            S[3][0] = fmaf(a3, b0, S[3][0]); S[3][1] = fmaf(a3, b1, S[3][1]);
            S[3][2] = fmaf(a3, b2, S[3][2]); S[3][3] = fmaf(a3, b3, S[3][3]);
        }

        float mt[4];
#pragma unroll
        for (int i = 0; i < 4; i++)
            mt[i] = fmaxf(fmaxf(S[i][0], S[i][1]), fmaxf(S[i][2], S[i][3]));
#pragma unroll
        for (int off = 1; off < 16; off <<= 1)
#pragma unroll
            for (int i = 0; i < 4; i++)
                mt[i] = fmaxf(mt[i], __shfl_xor_sync(0xffffffffu, mt[i], off));

        float alpha[4];
#pragma unroll
        for (int i = 0; i < 4; i++) {
            float mn = fmaxf(m_[i], mt[i]);
            alpha[i] = __expf(m_[i] - mn);
            m_[i] = mn;
        }

        float ps[4] = {0.f, 0.f, 0.f, 0.f};
#pragma unroll
        for (int i = 0; i < 4; i++)
#pragma unroll
            for (int j = 0; j < 4; j++) {
                float p = __expf(S[i][j] - m_[i]);
                Ps[(ty4 + i) * 68 + tx4 + j] = p;
                ps[i] += p;
            }
#pragma unroll
        for (int off = 1; off < 16; off <<= 1)
#pragma unroll
            for (int i = 0; i < 4; i++)
                ps[i] += __shfl_xor_sync(0xffffffffu, ps[i], off);

#pragma unroll
        for (int i = 0; i < 4; i++) {
            l_[i] = l_[i] * alpha[i] + ps[i];
#pragma unroll
            for (int k = 0; k < 4; k++) O[i][k] *= alpha[i];
        }
        __syncthreads();

#pragma unroll 8
        for (int j = 0; j < 64; j++) {
            const float4 vv = *(const float4*)(Vs + j * 68 + tx4);
            float p0 = Ps[(ty4 + 0) * 68 + j];
            float p1 = Ps[(ty4 + 1) * 68 + j];
            float p2 = Ps[(ty4 + 2) * 68 + j];
            float p3 = Ps[(ty4 + 3) * 68 + j];
            O[0][0] = fmaf(p0, vv.x, O[0][0]); O[0][1] = fmaf(p0, vv.y, O[0][1]);
            O[0][2] = fmaf(p0, vv.z, O[0][2]); O[0][3] = fmaf(p0, vv.w, O[0][3]);
            O[1][0] = fmaf(p1, vv.x, O[1][0]); O[1][1] = fmaf(p1, vv.y, O[1][1]);
            O[1][2] = fmaf(p1, vv.z, O[1][2]); O[1][3] = fmaf(p1, vv.w, O[1][3]);
            O[2][0] = fmaf(p2, vv.x, O[2][0]); O[2][1] = fmaf(p2, vv.y, O[2][1]);
            O[2][2] = fmaf(p2, vv.z, O[2][2]); O[2][3] = fmaf(p2, vv.w, O[2][3]);
            O[3][0] = fmaf(p3, vv.x, O[3][0]); O[3][1] = fmaf(p3, vv.y, O[3][1]);
            O[3][2] = fmaf(p3, vv.z, O[3][2]); O[3][3] = fmaf(p3, vv.w, O[3][3]);
        }
    }

    // Epilogue: write bf16 hi/lo pairs
#pragma unroll
    for (int i = 0; i < 4; i++) {
        float inv = 1.0f / l_[i];
        size_t idx = (size_t)(b * N_ + n0 + ty4 + i) * C_ + h * D_ + tx4;
        __nv_bfloat16 hh[4], ll[4];
#pragma unroll
        for (int k = 0; k < 4; k++) {
            float v = O[i][k] * inv;
            hh[k] = __float2bfloat16(v);
            ll[k] = __float2bfloat16(v - __bfloat162float(hh[k]));
        }
        *(__nv_bfloat162*)(ohi + idx)     = __nv_bfloat162(hh[0], hh[1]);
        *(__nv_bfloat162*)(ohi + idx + 2) = __nv_bfloat162(hh[2], hh[3]);
        *(__nv_bfloat162*)(olo + idx)     = __nv_bfloat162(ll[0], ll[1]);
        *(__nv_bfloat162*)(olo + idx + 2) = __nv_bfloat162(ll[2], ll[3]);
    }
}

// ---------------------------------------------------------------------------
extern "C" void kernel_launch(void* const* d_in, const int* in_sizes, int n_in,
                              void* d_out, int out_size) {
    const float* x      = (const float*)d_in[0];  // (B,N,C)
    const float* ctx    = (const float*)d_in[1];  // (B,NC,2C)
    const float* w_qkv  = (const float*)d_in[2];  // (3C,C)
    const float* w_proj = (const float*)d_in[3];  // (C,C)
    const float* b_proj = (const float*)d_in[4];  // (C,)
    float* out = (float*)d_out;                   // (B,N,C)

    void *p;
    cudaGetSymbolAddress(&p, g_qkv);      float* qkvp = (float*)p;
    cudaGetSymbolAddress(&p, g_xhi);      __nv_bfloat16* xhi = (__nv_bfloat16*)p;
    cudaGetSymbolAddress(&p, g_xlo);      __nv_bfloat16* xlo = (__nv_bfloat16*)p;
    cudaGetSymbolAddress(&p, g_wqkv_hi);  __nv_bfloat16* wqh = (__nv_bfloat16*)p;
    cudaGetSymbolAddress(&p, g_wqkv_lo);  __nv_bfloat16* wql = (__nv_bfloat16*)p;
    cudaGetSymbolAddress(&p, g_wproj_hi); __nv_bfloat16* wph = (__nv_bfloat16*)p;
    cudaGetSymbolAddress(&p, g_wproj_lo); __nv_bfloat16* wpl = (__nv_bfloat16*)p;
    cudaGetSymbolAddress(&p, g_ahi);      __nv_bfloat16* ahi = (__nv_bfloat16*)p;
    cudaGetSymbolAddress(&p, g_alo);      __nv_bfloat16* alo = (__nv_bfloat16*)p;

    cudaFuncSetAttribute(gemm_mma<false>, cudaFuncAttributeMaxDynamicSharedMemorySize, GEMM_SMEM);
    cudaFuncSetAttribute(gemm_mma<true>,  cudaFuncAttributeMaxDynamicSharedMemorySize, GEMM_SMEM);
    cudaFuncSetAttribute(attn_kernel,     cudaFuncAttributeMaxDynamicSharedMemorySize, SMEM_ATTN);

    // 0) decompose inputs/weights into bf16 hi/lo
    {
        int n4x = B_ * N_ * C_ / 4;
        int n4q = 3 * C_ * C_ / 4;
        int n4p = C_ * C_ / 4;
        decomp_kernel<<<(n4x + 255) / 256, 256>>>(x, xhi, xlo, n4x);
        decomp_kernel<<<(n4q + 255) / 256, 256>>>(w_qkv, wqh, wql, n4q);
        decomp_kernel<<<(n4p + 255) / 256, 256>>>(w_proj, wph, wpl, n4p);
    }

    // 1) QKV projection: (4096,3072) via mma.sync bf16x3
    {
        dim3 grid(3 * C_ / 128, B_ * N_ / 128);
        gemm_mma<false><<<grid, 256, GEMM_SMEM>>>(xhi, xlo, wqh, wql, nullptr, qkvp,
                                                  B_ * N_, 3 * C_, C_);
    }

    // 2) Attention (SIMT fp32)
    {
        dim3 grid(N_ / 64, H_, B_);
        attn_kernel<<<grid, 256, SMEM_ATTN>>>(qkvp, ctx, ahi, alo);
    }

    // 3) Output projection with bias via mma.sync bf16x3
    {
        dim3 grid(C_ / 128, B_ * N_ / 128);
        gemm_mma<true><<<grid, 256, GEMM_SMEM>>>(ahi, alo, wph, wpl, b_proj, out,
                                                 B_ * N_, C_, C_);
    }
}

// round 4
// speedup vs baseline: 3.1392x; 2.1190x over previous
#include <cuda_runtime.h>
#include <cuda_bf16.h>
#include <cstdint>
#include <math.h>

// Problem constants (fixed by setup_inputs)
#define B_   4
#define N_   1024
#define C_   1024
#define H_   16
#define D_   64
#define NC_  256
#define M_   1280            // NC_ + N_
#define KVT  20              // M_/64 kv tiles

// ---------------------------------------------------------------------------
// Scratch (allocation-free rule: __device__ globals)
// ---------------------------------------------------------------------------
__device__ float         g_qkv[(size_t)B_ * N_ * 3 * C_];
__device__ __nv_bfloat16 g_xhi[(size_t)B_ * N_ * C_];
__device__ __nv_bfloat16 g_xlo[(size_t)B_ * N_ * C_];
__device__ __nv_bfloat16 g_wqkv_hi[(size_t)3 * C_ * C_];
__device__ __nv_bfloat16 g_wqkv_lo[(size_t)3 * C_ * C_];
__device__ __nv_bfloat16 g_wproj_hi[(size_t)C_ * C_];
__device__ __nv_bfloat16 g_wproj_lo[(size_t)C_ * C_];
__device__ __nv_bfloat16 g_ahi[(size_t)B_ * N_ * C_];
__device__ __nv_bfloat16 g_alo[(size_t)B_ * N_ * C_];
// attention operand buffers (per bh = b*H+h)
__device__ __nv_bfloat16 g_qh[(size_t)B_ * H_ * N_ * D_];
__device__ __nv_bfloat16 g_ql[(size_t)B_ * H_ * N_ * D_];
__device__ __nv_bfloat16 g_kh[(size_t)B_ * H_ * M_ * D_];
__device__ __nv_bfloat16 g_kl[(size_t)B_ * H_ * M_ * D_];
__device__ __nv_bfloat16 g_vth[(size_t)B_ * H_ * D_ * M_];   // transposed [d][kv]
__device__ __nv_bfloat16 g_vtl[(size_t)B_ * H_ * D_ * M_];

// ---------------------------------------------------------------------------
// Helpers (sm_100 baseline PTX only)
// ---------------------------------------------------------------------------
__device__ __forceinline__ uint32_t smem_u32(const void* p) {
    uint32_t a;
    asm("{ .reg .u64 t; cvta.to.shared.u64 t, %1; cvt.u32.u64 %0, t; }" : "=r"(a) : "l"(p));
    return a;
}
__device__ __forceinline__ void cpa16(uint32_t d, const void* g) {
    asm volatile("cp.async.cg.shared.global [%0], [%1], 16;" :: "r"(d), "l"(g));
}
__device__ __forceinline__ void cpa_commit() { asm volatile("cp.async.commit_group;"); }
template <int n> __device__ __forceinline__ void cpa_wait() {
    asm volatile("cp.async.wait_group %0;" :: "n"(n));
}
__device__ __forceinline__ uint32_t sw128(uint32_t off) { return off ^ ((off >> 3) & 0x70); }

__device__ __forceinline__ void ldsm_x4(uint32_t* r, uint32_t addr) {
    asm volatile("ldmatrix.sync.aligned.m8n8.x4.shared.b16 {%0,%1,%2,%3}, [%4];"
        : "=r"(r[0]), "=r"(r[1]), "=r"(r[2]), "=r"(r[3]) : "r"(addr));
}
__device__ __forceinline__ void mma_bf16(float* d, const uint32_t* a,
                                         uint32_t b0, uint32_t b1) {
    asm volatile(
        "mma.sync.aligned.m16n8k16.row.col.f32.bf16.bf16.f32 "
        "{%0,%1,%2,%3},{%4,%5,%6,%7},{%8,%9},{%0,%1,%2,%3};"
        : "+f"(d[0]), "+f"(d[1]), "+f"(d[2]), "+f"(d[3])
        : "r"(a[0]), "r"(a[1]), "r"(a[2]), "r"(a[3]), "r"(b0), "r"(b1));
}
__device__ __forceinline__ uint32_t pack_bf16(float a, float b) {
    __nv_bfloat162 t = __floats2bfloat162_rn(a, b);
    return *(uint32_t*)&t;
}

// ---------------------------------------------------------------------------
// fp32 -> bf16 hi/lo decomposition
// ---------------------------------------------------------------------------
__global__ void decomp_kernel(const float* __restrict__ in,
                              __nv_bfloat16* __restrict__ hi,
                              __nv_bfloat16* __restrict__ lo, int n4) {
    int i = blockIdx.x * blockDim.x + threadIdx.x;
    if (i >= n4) return;
    float4 v = ((const float4*)in)[i];
    __nv_bfloat16 h[4], l[4];
    float x[4] = {v.x, v.y, v.z, v.w};
#pragma unroll
    for (int k = 0; k < 4; k++) {
        h[k] = __float2bfloat16(x[k]);
        l[k] = __float2bfloat16(x[k] - __bfloat162float(h[k]));
    }
    ((__nv_bfloat162*)hi)[i * 2 + 0] = __nv_bfloat162(h[0], h[1]);
    ((__nv_bfloat162*)hi)[i * 2 + 1] = __nv_bfloat162(h[2], h[3]);
    ((__nv_bfloat162*)lo)[i * 2 + 0] = __nv_bfloat162(l[0], l[1]);
    ((__nv_bfloat162*)lo)[i * 2 + 1] = __nv_bfloat162(l[2], l[3]);
}

// ---------------------------------------------------------------------------
// Prep: Q hi/lo (scale folded) from qkv slot 0
// ---------------------------------------------------------------------------
__global__ void prepq_kernel(const float* __restrict__ qkv,
                             __nv_bfloat16* __restrict__ qh,
                             __nv_bfloat16* __restrict__ ql) {
    int t = blockIdx.x * blockDim.x + threadIdx.x;   // 0 .. 1M-1
    int d4 = t & 15;
    int h  = (t >> 4) & 15;
    int n  = (t >> 8) & 1023;
    int b  = t >> 18;
    const float* src = qkv + (((size_t)(b * N_ + n)) * 3 + 0) * C_ + h * D_ + d4 * 4;
    float4 v = *(const float4*)src;
    float x[4] = {v.x * 0.125f, v.y * 0.125f, v.z * 0.125f, v.w * 0.125f};
    __nv_bfloat16 hh[4], ll[4];
#pragma unroll
    for (int k = 0; k < 4; k++) {
        hh[k] = __float2bfloat16(x[k]);
        ll[k] = __float2bfloat16(x[k] - __bfloat162float(hh[k]));
    }
    size_t o = (((size_t)(b * H_ + h)) * N_ + n) * D_ + d4 * 4;
    *(__nv_bfloat162*)(qh + o)     = __nv_bfloat162(hh[0], hh[1]);
    *(__nv_bfloat162*)(qh + o + 2) = __nv_bfloat162(hh[2], hh[3]);
    *(__nv_bfloat162*)(ql + o)     = __nv_bfloat162(ll[0], ll[1]);
    *(__nv_bfloat162*)(ql + o + 2) = __nv_bfloat162(ll[2], ll[3]);
}

// ---------------------------------------------------------------------------
// Prep: K hi/lo [bh][M][D] + Vt hi/lo [bh][D][M] (smem-staged transpose)
// grid (KVT chunks of 64 kv, 64 bh), 256 threads
// ---------------------------------------------------------------------------
__global__ void prepkv_kernel(const float* __restrict__ qkv, const float* __restrict__ ctx,
                              __nv_bfloat16* __restrict__ kh, __nv_bfloat16* __restrict__ kl,
                              __nv_bfloat16* __restrict__ vth, __nv_bfloat16* __restrict__ vtl) {
    __shared__ float sv[64][65];
    const int tid = threadIdx.x;
    const int kv0 = blockIdx.x * 64;
    const int bh  = blockIdx.y;
    const int b = bh >> 4, h = bh & 15;

#pragma unroll
    for (int it = 0; it < 4; it++) {
        int idx = tid + it * 256;
        int r  = idx >> 4;          // kv row 0..63
        int dc = idx & 15;          // d chunk (4 floats)
        int kv = kv0 + r;
        const float *pk, *pv;
        if (kv < NC_) {
            const float* base = ctx + (((size_t)(b * NC_ + kv)) * 2 + 0) * C_ + h * D_ + dc * 4;
            pk = base; pv = base + C_;
        } else {
            const float* base = qkv + (((size_t)(b * N_ + kv - NC_)) * 3 + 1) * C_ + h * D_ + dc * 4;
            pk = base; pv = base + C_;
        }
        float4 kvec = *(const float4*)pk;
        float4 vvec = *(const float4*)pv;
        // K: coalesced hi/lo write
        float kx[4] = {kvec.x, kvec.y, kvec.z, kvec.w};
        __nv_bfloat16 hh[4], ll[4];
#pragma unroll
        for (int q = 0; q < 4; q++) {
            hh[q] = __float2bfloat16(kx[q]);
            ll[q] = __float2bfloat16(kx[q] - __bfloat162float(hh[q]));
        }
        size_t o = (((size_t)bh) * M_ + kv) * D_ + dc * 4;
        *(__nv_bfloat162*)(kh + o)     = __nv_bfloat162(hh[0], hh[1]);
        *(__nv_bfloat162*)(kh + o + 2) = __nv_bfloat162(hh[2], hh[3]);
        *(__nv_bfloat162*)(kl + o)     = __nv_bfloat162(ll[0], ll[1]);
        *(__nv_bfloat162*)(kl + o + 2) = __nv_bfloat162(ll[2], ll[3]);
        // V: stage fp32 for transpose
        sv[r][dc * 4 + 0] = vvec.x; sv[r][dc * 4 + 1] = vvec.y;
        sv[r][dc * 4 + 2] = vvec.z; sv[r][dc * 4 + 3] = vvec.w;
    }
    __syncthreads();

    // write Vt rows: thread -> (d = idx>>2, kv quarter = idx&3) : 16 kv values
#pragma unroll
    for (int it = 0; it < 1; it++) {
        int idx = tid;
        int d  = idx >> 2;
        int q4 = (idx & 3) * 16;
        size_t o = ((size_t)bh) * D_ * M_ + (size_t)d * M_ + kv0 + q4;
#pragma unroll
        for (int k2 = 0; k2 < 8; k2++) {
            float v0 = sv[q4 + k2 * 2][d];
            float v1 = sv[q4 + k2 * 2 + 1][d];
            __nv_bfloat16 h0 = __float2bfloat16(v0);
            __nv_bfloat16 h1 = __float2bfloat16(v1);
            __nv_bfloat16 l0 = __float2bfloat16(v0 - __bfloat162float(h0));
            __nv_bfloat16 l1 = __float2bfloat16(v1 - __bfloat162float(h1));
            *(__nv_bfloat162*)(vth + o + k2 * 2) = __nv_bfloat162(h0, h1);
            *(__nv_bfloat162*)(vtl + o + k2 * 2) = __nv_bfloat162(l0, l1);
        }
    }
}

// ---------------------------------------------------------------------------
// mma.sync bf16x3 GEMM (unchanged from round 3)
// ---------------------------------------------------------------------------
#define GKC 64
#define TILE_B 16384
#define STAGE_BYTES (4 * TILE_B)
#define GEMM_SMEM (2 * STAGE_BYTES + 1024)

__device__ __forceinline__ void load_tile(const __nv_bfloat16* __restrict__ src,
                                          int rbase, int K, int k0,
                                          uint32_t tb, int tid) {
#pragma unroll
    for (int i = 0; i < 4; i++) {
        int idx = tid + i * 256;
        int r = idx >> 3;
        int c = idx & 7;
        const void* g = src + (size_t)(rbase + r) * K + k0 + c * 8;
        cpa16(tb + sw128((uint32_t)(r * 128 + c * 16)), g);
    }
}

template <bool BIAS>
__global__ __launch_bounds__(256) void gemm_mma(
    const __nv_bfloat16* __restrict__ Ahi, const __nv_bfloat16* __restrict__ Alo,
    const __nv_bfloat16* __restrict__ Bhi, const __nv_bfloat16* __restrict__ Blo,
    const float* __restrict__ bias, float* __restrict__ Cout,
    int M, int N, int K)
{
    extern __shared__ char sm[];
    const uint32_t tiles = (smem_u32(sm) + 1023) & ~1023u;

    const int tid  = threadIdx.x;
    const int lane = tid & 31;
    const int wid  = tid >> 5;
    const int wm0  = (wid >> 2) * 64;
    const int wn0  = (wid & 3) * 32;
    const int bm = blockIdx.y * 128;
    const int bn = blockIdx.x * 128;

    const int lr = lane & 15;
    const int lc = (lane >> 4) << 4;

    float acc[4][4][4];
#pragma unroll
    for (int i = 0; i < 4; i++)
#pragma unroll
        for (int j = 0; j < 4; j++)
#pragma unroll
            for (int t = 0; t < 4; t++) acc[i][j][t] = 0.0f;

    const int NCH = K / GKC;

    {
        uint32_t st = tiles;
        load_tile(Ahi, bm, K, 0, st,              tid);
        load_tile(Alo, bm, K, 0, st + TILE_B,     tid);
        load_tile(Bhi, bn, K, 0, st + 2 * TILE_B, tid);
        load_tile(Blo, bn, K, 0, st + 3 * TILE_B, tid);
        cpa_commit();
    }

    for (int k = 0; k < NCH; k++) {
        const int b = k & 1;
        if (k + 1 < NCH) {
            const int nb = (k + 1) & 1;
            uint32_t st = tiles + nb * STAGE_BYTES;
            const int k0 = (k + 1) * GKC;
            load_tile(Ahi, bm, K, k0, st,              tid);
            load_tile(Alo, bm, K, k0, st + TILE_B,     tid);
            load_tile(Bhi, bn, K, k0, st + 2 * TILE_B, tid);
            load_tile(Blo, bn, K, k0, st + 3 * TILE_B, tid);
            cpa_commit();
            cpa_wait<1>();
        } else {
            cpa_wait<0>();
        }
        __syncthreads();

        const uint32_t st  = tiles + b * STAGE_BYTES;
        const uint32_t tAh = st;
        const uint32_t tAl = st + TILE_B;
        const uint32_t tBh = st + 2 * TILE_B;
        const uint32_t tBl = st + 3 * TILE_B;

#pragma unroll
        for (int kk = 0; kk < 4; kk++) {
            uint32_t ah[4][4], al[4][4], bh[2][4], bl[2][4];
#pragma unroll
            for (int mt = 0; mt < 4; mt++) {
                uint32_t o = sw128((uint32_t)((wm0 + mt * 16 + lr) * 128 + kk * 32 + lc));
                ldsm_x4(ah[mt], tAh + o);
                ldsm_x4(al[mt], tAl + o);
            }
#pragma unroll
            for (int ng = 0; ng < 2; ng++) {
                uint32_t o = sw128((uint32_t)((wn0 + ng * 16 + lr) * 128 + kk * 32 + lc));
                ldsm_x4(bh[ng], tBh + o);
                ldsm_x4(bl[ng], tBl + o);
            }
#pragma unroll
            for (int mt = 0; mt < 4; mt++)
#pragma unroll
                for (int nt = 0; nt < 4; nt++) {
                    const int ng = nt >> 1, s = nt & 1;
                    mma_bf16(acc[mt][nt], ah[mt], bh[ng][s], bh[ng][2 + s]);
                    mma_bf16(acc[mt][nt], ah[mt], bl[ng][s], bl[ng][2 + s]);
                    mma_bf16(acc[mt][nt], al[mt], bh[ng][s], bh[ng][2 + s]);
                }
        }
        __syncthreads();
    }

    const int gq = lane >> 2;
    const int tg = lane & 3;
#pragma unroll
    for (int mt = 0; mt < 4; mt++) {
        const int row0 = bm + wm0 + mt * 16 + gq;
#pragma unroll
        for (int nt = 0; nt < 4; nt++) {
            const int col = bn + wn0 + nt * 8 + tg * 2;
            float2 v0 = make_float2(acc[mt][nt][0], acc[mt][nt][1]);
            float2 v1 = make_float2(acc[mt][nt][2], acc[mt][nt][3]);
            if (BIAS) {
                float b0v = bias[col], b1v = bias[col + 1];
                v0.x += b0v; v0.y += b1v;
                v1.x += b0v; v1.y += b1v;
            }
            *(float2*)(Cout + (size_t)row0 * N + col)       = v0;
            *(float2*)(Cout + (size_t)(row0 + 8) * N + col) = v1;
        }
    }
}

// ---------------------------------------------------------------------------
// Flash attention via mma.sync bf16x3
// CTA: 128 queries x (b,h). 8 warps x 16 rows. KV tiles of 64, 2-stage cp.async.
// smem: Qh/Ql 16KB each + 2 stages x (Kh,Kl,Vth,Vtl 8KB each) = 96KB
// ---------------------------------------------------------------------------
#define AT_STAGE 32768
#define AT_SMEM (32768 + 2 * AT_STAGE + 1024)

__device__ __forceinline__ void at_load_kv(
    const __nv_bfloat16* kh, const __nv_bfloat16* kl,
    const __nv_bfloat16* vth, const __nv_bfloat16* vtl,
    int kv0, uint32_t st, int tid)
{
#pragma unroll
    for (int i = 0; i < 2; i++) {
        int idx = tid + i * 256;
        int r = idx >> 3;        // 0..63
        int c = idx & 7;
        uint32_t so = sw128((uint32_t)(r * 128 + c * 16));
        cpa16(st + so,           kh  + (size_t)(kv0 + r) * D_ + c * 8);
        cpa16(st + 8192 + so,    kl  + (size_t)(kv0 + r) * D_ + c * 8);
        cpa16(st + 16384 + so,   vth + (size_t)r * M_ + kv0 + c * 8);
        cpa16(st + 24576 + so,   vtl + (size_t)r * M_ + kv0 + c * 8);
    }
}

__global__ __launch_bounds__(256) void attn_mma(
    const __nv_bfloat16* __restrict__ Qh, const __nv_bfloat16* __restrict__ Ql,
    const __nv_bfloat16* __restrict__ Kh, const __nv_bfloat16* __restrict__ Kl,
    const __nv_bfloat16* __restrict__ Vth, const __nv_bfloat16* __restrict__ Vtl,
    __nv_bfloat16* __restrict__ ohi, __nv_bfloat16* __restrict__ olo)
{
    extern __shared__ char sm[];
    const uint32_t base = (smem_u32(sm) + 1023) & ~1023u;
    const uint32_t sQh = base, sQl = base + 16384;
    const uint32_t sStage = base + 32768;

    const int tid  = threadIdx.x;
    const int lane = tid & 31;
    const int wid  = tid >> 5;
    const int qt = blockIdx.x;      // 0..7 (128-query tile)
    const int h  = blockIdx.y;
    const int b  = blockIdx.z;
    const int bh = b * H_ + h;

    const __nv_bfloat16* qhg = Qh + ((size_t)bh * N_ + qt * 128) * D_;
    const __nv_bfloat16* qlg = Ql + ((size_t)bh * N_ + qt * 128) * D_;
    const __nv_bfloat16* khg = Kh + (size_t)bh * M_ * D_;
    const __nv_bfloat16* klg = Kl + (size_t)bh * M_ * D_;
    const __nv_bfloat16* vhg = Vth + (size_t)bh * D_ * M_;
    const __nv_bfloat16* vlg = Vtl + (size_t)bh * D_ * M_;

    // Q tile load (128 rows x 128B, both hi and lo) + stage 0, one commit group
#pragma unroll
    for (int i = 0; i < 4; i++) {
        int idx = tid + i * 256;
        int r = idx >> 3;
        int c = idx & 7;
        uint32_t so = sw128((uint32_t)(r * 128 + c * 16));
        cpa16(sQh + so, qhg + (size_t)r * D_ + c * 8);
        cpa16(sQl + so, qlg + (size_t)r * D_ + c * 8);
    }
    at_load_kv(khg, klg, vhg, vlg, 0, sStage, tid);
    cpa_commit();

    const int lr = lane & 15;
    const int lc = (lane >> 4) << 4;
    const int w16 = wid * 16;

    uint32_t qfh[4][4], qfl[4][4];
    float O[8][4];
#pragma unroll
    for (int nt = 0; nt < 8; nt++)
#pragma unroll
        for (int t = 0; t < 4; t++) O[nt][t] = 0.0f;
    float m0 = -1e30f, m1 = -1e30f, l0 = 0.0f, l1 = 0.0f;

    for (int kt = 0; kt < KVT; kt++) {
        const int bs = kt & 1;
        if (kt + 1 < KVT) {
            at_load_kv(khg, klg, vhg, vlg, (kt + 1) * 64,
                       sStage + ((kt + 1) & 1) * AT_STAGE, tid);
            cpa_commit();
            cpa_wait<1>();
        } else {
            cpa_wait<0>();
        }
        __syncthreads();

        if (kt == 0) {
#pragma unroll
            for (int kk = 0; kk < 4; kk++) {
                uint32_t o = sw128((uint32_t)((w16 + lr) * 128 + kk * 32 + lc));
                ldsm_x4(qfh[kk], sQh + o);
                ldsm_x4(qfl[kk], sQl + o);
            }
        }

        const uint32_t tK  = sStage + bs * AT_STAGE;
        const uint32_t tKl = tK + 8192;
        const uint32_t tV  = tK + 16384;
        const uint32_t tVl = tK + 24576;

        // ---- S = Q . K^T (x3) ----
        float S[8][4];
#pragma unroll
        for (int nt = 0; nt < 8; nt++)
#pragma unroll
            for (int t = 0; t < 4; t++) S[nt][t] = 0.0f;

#pragma unroll
        for (int kk = 0; kk < 4; kk++) {
            uint32_t bhf[4][4], blf[4][4];
#pragma unroll
            for (int ng = 0; ng < 4; ng++) {
                uint32_t o = sw128((uint32_t)((ng * 16 + lr) * 128 + kk * 32 + lc));
                ldsm_x4(bhf[ng], tK + o);
                ldsm_x4(blf[ng], tKl + o);
            }
#pragma unroll
            for (int ng = 0; ng < 4; ng++)
#pragma unroll
                for (int s = 0; s < 2; s++) {
                    const int nt = ng * 2 + s;
                    mma_bf16(S[nt], qfh[kk], bhf[ng][s], bhf[ng][2 + s]);
                    mma_bf16(S[nt], qfh[kk], blf[ng][s], blf[ng][2 + s]);
                    mma_bf16(S[nt], qfl[kk], bhf[ng][s], bhf[ng][2 + s]);
                }
        }

        // ---- online softmax ----
        float mt0 = -1e30f, mt1 = -1e30f;
#pragma unroll
        for (int nt = 0; nt < 8; nt++) {
            mt0 = fmaxf(mt0, fmaxf(S[nt][0], S[nt][1]));
            mt1 = fmaxf(mt1, fmaxf(S[nt][2], S[nt][3]));
        }
        mt0 = fmaxf(mt0, __shfl_xor_sync(0xffffffffu, mt0, 1));
        mt0 = fmaxf(mt0, __shfl_xor_sync(0xffffffffu, mt0, 2));
        mt1 = fmaxf(mt1, __shfl_xor_sync(0xffffffffu, mt1, 1));
        mt1 = fmaxf(mt1, __shfl_xor_sync(0xffffffffu, mt1, 2));

        float mn0 = fmaxf(m0, mt0), mn1 = fmaxf(m1, mt1);
        float a0 = __expf(m0 - mn0), a1 = __expf(m1 - mn1);
        m0 = mn0; m1 = mn1;

        float rs0 = 0.0f, rs1 = 0.0f;
#pragma unroll
        for (int nt = 0; nt < 8; nt++) {
            S[nt][0] = __expf(S[nt][0] - m0);
            S[nt][1] = __expf(S[nt][1] - m0);
            S[nt][2] = __expf(S[nt][2] - m1);
            S[nt][3] = __expf(S[nt][3] - m1);
            rs0 += S[nt][0] + S[nt][1];
            rs1 += S[nt][2] + S[nt][3];
        }
        rs0 += __shfl_xor_sync(0xffffffffu, rs0, 1);
        rs0 += __shfl_xor_sync(0xffffffffu, rs0, 2);
        rs1 += __shfl_xor_sync(0xffffffffu, rs1, 1);
        rs1 += __shfl_xor_sync(0xffffffffu, rs1, 2);
        l0 = l0 * a0 + rs0;
        l1 = l1 * a1 + rs1;

#pragma unroll
        for (int nt = 0; nt < 8; nt++) {
            O[nt][0] *= a0; O[nt][1] *= a0;
            O[nt][2] *= a1; O[nt][3] *= a1;
        }

        // ---- pack P hi/lo A-fragments ----
        uint32_t ph[4][4], pl[4][4];
#pragma unroll
        for (int j = 0; j < 4; j++) {
            float v[8] = {S[2 * j][0], S[2 * j][1], S[2 * j][2], S[2 * j][3],
                          S[2 * j + 1][0], S[2 * j + 1][1], S[2 * j + 1][2], S[2 * j + 1][3]};
            float rhi[8], rlo[8];
#pragma unroll
            for (int q = 0; q < 8; q++) {
                __nv_bfloat16 hb = __float2bfloat16(v[q]);
                rhi[q] = __bfloat162float(hb);
                rlo[q] = v[q] - rhi[q];
            }
            ph[j][0] = pack_bf16(rhi[0], rhi[1]);
            ph[j][1] = pack_bf16(rhi[2], rhi[3]);
            ph[j][2] = pack_bf16(rhi[4], rhi[5]);
            ph[j][3] = pack_bf16(rhi[6], rhi[7]);
            pl[j][0] = pack_bf16(rlo[0], rlo[1]);
            pl[j][1] = pack_bf16(rlo[2], rlo[3]);
            pl[j][2] = pack_bf16(rlo[4], rlo[5]);
            pl[j][3] = pack_bf16(rlo[6], rlo[7]);
        }

        // ---- O += P . Vt^T (x3) ----
#pragma unroll
        for (int j = 0; j < 4; j++) {
            uint32_t vhf[4][4], vlf[4][4];
#pragma unroll
            for (int ng = 0; ng < 4; ng++) {
                uint32_t o = sw128((uint32_t)((ng * 16 + lr) * 128 + j * 32 + lc));
                ldsm_x4(vhf[ng], tV + o);
                ldsm_x4(vlf[ng], tVl + o);
            }
#pragma unroll
            for (int ng = 0; ng < 4; ng++)
#pragma unroll
                for (int s = 0; s < 2; s++) {
                    const int nt = ng * 2 + s;
                    mma_bf16(O[nt], ph[j], vhf[ng][s], vhf[ng][2 + s]);
                    mma_bf16(O[nt], ph[j], vlf[ng][s], vlf[ng][2 + s]);
                    mma_bf16(O[nt], pl[j], vhf[ng][s], vhf[ng][2 + s]);
                }
        }
        __syncthreads();
    }

    // ---- epilogue: O/l -> bf16 hi/lo at (b, n, h*64 + d) ----
    const float inv0 = 1.0f / l0, inv1 = 1.0f / l1;
    const int g  = lane >> 2;
    const int tg = lane & 3;
    const int n0 = qt * 128 + w16 + g;
#pragma unroll
    for (int nt = 0; nt < 8; nt++) {
        const int col = h * D_ + nt * 8 + tg * 2;
        {
            float v0 = O[nt][0] * inv0, v1 = O[nt][1] * inv0;
            __nv_bfloat16 h0 = __float2bfloat16(v0), h1 = __float2bfloat16(v1);
            __nv_bfloat16 q0 = __float2bfloat16(v0 - __bfloat162float(h0));
            __nv_bfloat16 q1 = __float2bfloat16(v1 - __bfloat162float(h1));
            size_t o = (size_t)(b * N_ + n0) * C_ + col;
            *(__nv_bfloat162*)(ohi + o) = __nv_bfloat162(h0, h1);
            *(__nv_bfloat162*)(olo + o) = __nv_bfloat162(q0, q1);
        }
        {
            float v0 = O[nt][2] * inv1, v1 = O[nt][3] * inv1;
            __nv_bfloat16 h0 = __float2bfloat16(v0), h1 = __float2bfloat16(v1);
            __nv_bfloat16 q0 = __float2bfloat16(v0 - __bfloat162float(h0));
            __nv_bfloat16 q1 = __float2bfloat16(v1 - __bfloat162float(h1));
            size_t o = (size_t)(b * N_ + n0 + 8) * C_ + col;
            *(__nv_bfloat162*)(ohi + o) = __nv_bfloat162(h0, h1);
            *(__nv_bfloat162*)(olo + o) = __nv_bfloat162(q0, q1);
        }
    }
}

// ---------------------------------------------------------------------------
extern "C" void kernel_launch(void* const* d_in, const int* in_sizes, int n_in,
                              void* d_out, int out_size) {
    const float* x      = (const float*)d_in[0];
    const float* ctx    = (const float*)d_in[1];
    const float* w_qkv  = (const float*)d_in[2];
    const float* w_proj = (const float*)d_in[3];
    const float* b_proj = (const float*)d_in[4];
    float* out = (float*)d_out;

    void *p;
    cudaGetSymbolAddress(&p, g_qkv);      float* qkvp = (float*)p;
    cudaGetSymbolAddress(&p, g_xhi);      __nv_bfloat16* xhi = (__nv_bfloat16*)p;
    cudaGetSymbolAddress(&p, g_xlo);      __nv_bfloat16* xlo = (__nv_bfloat16*)p;
    cudaGetSymbolAddress(&p, g_wqkv_hi);  __nv_bfloat16* wqh = (__nv_bfloat16*)p;
    cudaGetSymbolAddress(&p, g_wqkv_lo);  __nv_bfloat16* wql = (__nv_bfloat16*)p;
    cudaGetSymbolAddress(&p, g_wproj_hi); __nv_bfloat16* wph = (__nv_bfloat16*)p;
    cudaGetSymbolAddress(&p, g_wproj_lo); __nv_bfloat16* wpl = (__nv_bfloat16*)p;
    cudaGetSymbolAddress(&p, g_ahi);      __nv_bfloat16* ahi = (__nv_bfloat16*)p;
    cudaGetSymbolAddress(&p, g_alo);      __nv_bfloat16* alo = (__nv_bfloat16*)p;
    cudaGetSymbolAddress(&p, g_qh);       __nv_bfloat16* qh  = (__nv_bfloat16*)p;
    cudaGetSymbolAddress(&p, g_ql);       __nv_bfloat16* ql  = (__nv_bfloat16*)p;
    cudaGetSymbolAddress(&p, g_kh);       __nv_bfloat16* kh  = (__nv_bfloat16*)p;
    cudaGetSymbolAddress(&p, g_kl);       __nv_bfloat16* kl  = (__nv_bfloat16*)p;
    cudaGetSymbolAddress(&p, g_vth);      __nv_bfloat16* vth = (__nv_bfloat16*)p;
    cudaGetSymbolAddress(&p, g_vtl);      __nv_bfloat16* vtl = (__nv_bfloat16*)p;

    cudaFuncSetAttribute(gemm_mma<false>, cudaFuncAttributeMaxDynamicSharedMemorySize, GEMM_SMEM);
    cudaFuncSetAttribute(gemm_mma<true>,  cudaFuncAttributeMaxDynamicSharedMemorySize, GEMM_SMEM);
    cudaFuncSetAttribute(attn_mma,        cudaFuncAttributeMaxDynamicSharedMemorySize, AT_SMEM);

    // 0) decompose inputs/weights
    {
        int n4x = B_ * N_ * C_ / 4;
        int n4q = 3 * C_ * C_ / 4;
        int n4p = C_ * C_ / 4;
        decomp_kernel<<<(n4x + 255) / 256, 256>>>(x, xhi, xlo, n4x);
        decomp_kernel<<<(n4q + 255) / 256, 256>>>(w_qkv, wqh, wql, n4q);
        decomp_kernel<<<(n4p + 255) / 256, 256>>>(w_proj, wph, wpl, n4p);
    }

    // 1) QKV projection
    {
        dim3 grid(3 * C_ / 128, B_ * N_ / 128);
        gemm_mma<false><<<grid, 256, GEMM_SMEM>>>(xhi, xlo, wqh, wql, nullptr, qkvp,
                                                  B_ * N_, 3 * C_, C_);
    }

    // 1.5) attention operand prep
    {
        prepq_kernel<<<4096, 256>>>(qkvp, qh, ql);
        dim3 grid(KVT, B_ * H_);
        prepkv_kernel<<<grid, 256>>>(qkvp, ctx, kh, kl, vth, vtl);
    }

    // 2) Attention via mma.sync
    {
        dim3 grid(N_ / 128, H_, B_);
        attn_mma<<<grid, 256, AT_SMEM>>>(qh, ql, kh, kl, vth, vtl, ahi, alo);
    }

    // 3) Output projection with bias
    {
        dim3 grid(C_ / 128, B_ * N_ / 128);
        gemm_mma<true><<<grid, 256, GEMM_SMEM>>>(ahi, alo, wph, wpl, b_proj, out,
                                                 B_ * N_, C_, C_);
    }
}

// round 6
// speedup vs baseline: 4.3978x; 1.4009x over previous
#include <cuda_runtime.h>
#include <cuda_fp16.h>
#include <cstdint>
#include <math.h>

// Problem constants (fixed by setup_inputs)
#define B_   4
#define N_   1024
#define C_   1024
#define H_   16
#define D_   64
#define NC_  256
#define M_   1280            // NC_ + N_
#define KVT  20              // M_/64 kv tiles

// ---------------------------------------------------------------------------
// Scratch (allocation-free rule: __device__ globals)
// ---------------------------------------------------------------------------
__device__ float  g_qkv[(size_t)B_ * N_ * 3 * C_];
__device__ __half g_xh[(size_t)B_ * N_ * C_];                 // x fp16 single
__device__ __half g_wqkv_hi[(size_t)3 * C_ * C_];
__device__ __half g_wqkv_lo[(size_t)3 * C_ * C_];
__device__ __half g_wproj_hi[(size_t)C_ * C_];
__device__ __half g_wproj_lo[(size_t)C_ * C_];
__device__ __half g_ah[(size_t)B_ * N_ * C_];                 // attn out fp16 single
// attention operand buffers (per bh = b*H+h)
__device__ __half g_qh[(size_t)B_ * H_ * N_ * D_];            // Q fp16 single (scaled)
__device__ __half g_kh[(size_t)B_ * H_ * M_ * D_];
__device__ __half g_kl[(size_t)B_ * H_ * M_ * D_];
__device__ __half g_vth[(size_t)B_ * H_ * D_ * M_];           // V^T [d][kv]
__device__ __half g_vtl[(size_t)B_ * H_ * D_ * M_];

// ---------------------------------------------------------------------------
// Helpers (sm_100 baseline PTX only)
// ---------------------------------------------------------------------------
__device__ __forceinline__ uint32_t smem_u32(const void* p) {
    uint32_t a;
    asm("{ .reg .u64 t; cvta.to.shared.u64 t, %1; cvt.u32.u64 %0, t; }" : "=r"(a) : "l"(p));
    return a;
}
__device__ __forceinline__ void cpa16(uint32_t d, const void* g) {
    asm volatile("cp.async.cg.shared.global [%0], [%1], 16;" :: "r"(d), "l"(g));
}
__device__ __forceinline__ void cpa_commit() { asm volatile("cp.async.commit_group;"); }
template <int n> __device__ __forceinline__ void cpa_wait() {
    asm volatile("cp.async.wait_group %0;" :: "n"(n));
}
__device__ __forceinline__ uint32_t sw128(uint32_t off) { return off ^ ((off >> 3) & 0x70); }

__device__ __forceinline__ void ldsm_x4(uint32_t* r, uint32_t addr) {
    asm volatile("ldmatrix.sync.aligned.m8n8.x4.shared.b16 {%0,%1,%2,%3}, [%4];"
        : "=r"(r[0]), "=r"(r[1]), "=r"(r[2]), "=r"(r[3]) : "r"(addr));
}
__device__ __forceinline__ void mma_fp16(float* d, const uint32_t* a,
                                         uint32_t b0, uint32_t b1) {
    asm volatile(
        "mma.sync.aligned.m16n8k16.row.col.f32.f16.f16.f32 "
        "{%0,%1,%2,%3},{%4,%5,%6,%7},{%8,%9},{%0,%1,%2,%3};"
        : "+f"(d[0]), "+f"(d[1]), "+f"(d[2]), "+f"(d[3])
        : "r"(a[0]), "r"(a[1]), "r"(a[2]), "r"(a[3]), "r"(b0), "r"(b1));
}
__device__ __forceinline__ uint32_t pack_h2(float a, float b) {
    __half2 t = __floats2half2_rn(a, b);
    return *(uint32_t*)&t;
}

// ---------------------------------------------------------------------------
// fp32 -> fp16 single / hi-lo decomposition
// ---------------------------------------------------------------------------
__global__ void decomp_h(const float* __restrict__ in, __half* __restrict__ o, int n4) {
    int i = blockIdx.x * blockDim.x + threadIdx.x;
    if (i >= n4) return;
    float4 v = ((const float4*)in)[i];
    ((uint32_t*)o)[i * 2 + 0] = pack_h2(v.x, v.y);
    ((uint32_t*)o)[i * 2 + 1] = pack_h2(v.z, v.w);
}
__global__ void decomp_hl(const float* __restrict__ in,
                          __half* __restrict__ hi, __half* __restrict__ lo, int n4) {
    int i = blockIdx.x * blockDim.x + threadIdx.x;
    if (i >= n4) return;
    float4 v = ((const float4*)in)[i];
    float x[4] = {v.x, v.y, v.z, v.w};
    float h[4], l[4];
#pragma unroll
    for (int k = 0; k < 4; k++) {
        h[k] = __half2float(__float2half_rn(x[k]));
        l[k] = x[k] - h[k];
    }
    ((uint32_t*)hi)[i * 2 + 0] = pack_h2(h[0], h[1]);
    ((uint32_t*)hi)[i * 2 + 1] = pack_h2(h[2], h[3]);
    ((uint32_t*)lo)[i * 2 + 0] = pack_h2(l[0], l[1]);
    ((uint32_t*)lo)[i * 2 + 1] = pack_h2(l[2], l[3]);
}

// ---------------------------------------------------------------------------
// Prep: Q fp16 single (scale folded), layout [bh][n][d]
// ---------------------------------------------------------------------------
__global__ void prepq_kernel(const float* __restrict__ qkv, __half* __restrict__ qh) {
    int t = blockIdx.x * blockDim.x + threadIdx.x;   // 1M threads
    int d4 = t & 15;
    int h  = (t >> 4) & 15;
    int n  = (t >> 8) & 1023;
    int b  = t >> 18;
    const float* src = qkv + (((size_t)(b * N_ + n)) * 3 + 0) * C_ + h * D_ + d4 * 4;
    float4 v = *(const float4*)src;
    size_t o = (((size_t)(b * H_ + h)) * N_ + n) * D_ + d4 * 4;
    *(uint32_t*)(qh + o)     = pack_h2(v.x * 0.125f, v.y * 0.125f);
    *(uint32_t*)(qh + o + 2) = pack_h2(v.z * 0.125f, v.w * 0.125f);
}

// ---------------------------------------------------------------------------
// Prep: K fp16 hi/lo [bh][M][D] + Vt fp16 hi/lo [bh][D][M]
// ---------------------------------------------------------------------------
__global__ void prepkv_kernel(const float* __restrict__ qkv, const float* __restrict__ ctx,
                              __half* __restrict__ kh, __half* __restrict__ kl,
                              __half* __restrict__ vth, __half* __restrict__ vtl) {
    __shared__ float sv[64][65];
    const int tid = threadIdx.x;
    const int kv0 = blockIdx.x * 64;
    const int bh  = blockIdx.y;
    const int b = bh >> 4, h = bh & 15;

#pragma unroll
    for (int it = 0; it < 4; it++) {
        int idx = tid + it * 256;
        int r  = idx >> 4;
        int dc = idx & 15;
        int kv = kv0 + r;
        const float *pk, *pv;
        if (kv < NC_) {
            const float* base = ctx + (((size_t)(b * NC_ + kv)) * 2 + 0) * C_ + h * D_ + dc * 4;
            pk = base; pv = base + C_;
        } else {
            const float* base = qkv + (((size_t)(b * N_ + kv - NC_)) * 3 + 1) * C_ + h * D_ + dc * 4;
            pk = base; pv = base + C_;
        }
        float4 kvec = *(const float4*)pk;
        float4 vvec = *(const float4*)pv;
        float kx[4] = {kvec.x, kvec.y, kvec.z, kvec.w};
        float hh[4], ll[4];
#pragma unroll
        for (int q = 0; q < 4; q++) {
            hh[q] = __half2float(__float2half_rn(kx[q]));
            ll[q] = kx[q] - hh[q];
        }
        size_t o = (((size_t)bh) * M_ + kv) * D_ + dc * 4;
        *(uint32_t*)(kh + o)     = pack_h2(hh[0], hh[1]);
        *(uint32_t*)(kh + o + 2) = pack_h2(hh[2], hh[3]);
        *(uint32_t*)(kl + o)     = pack_h2(ll[0], ll[1]);
        *(uint32_t*)(kl + o + 2) = pack_h2(ll[2], ll[3]);
        sv[r][dc * 4 + 0] = vvec.x; sv[r][dc * 4 + 1] = vvec.y;
        sv[r][dc * 4 + 2] = vvec.z; sv[r][dc * 4 + 3] = vvec.w;
    }
    __syncthreads();

    {
        int d  = tid >> 2;
        int q4 = (tid & 3) * 16;
        size_t o = ((size_t)bh) * D_ * M_ + (size_t)d * M_ + kv0 + q4;
#pragma unroll
        for (int k2 = 0; k2 < 8; k2++) {
            float v0 = sv[q4 + k2 * 2][d];
            float v1 = sv[q4 + k2 * 2 + 1][d];
            float h0 = __half2float(__float2half_rn(v0));
            float h1 = __half2float(__float2half_rn(v1));
            *(uint32_t*)(vth + o + k2 * 2) = pack_h2(h0, h1);
            *(uint32_t*)(vtl + o + k2 * 2) = pack_h2(v0 - h0, v1 - h1);
        }
    }
}

// ---------------------------------------------------------------------------
// mma.sync fp16 2-term GEMM: C[M,N] = A[M,K] @ B[N,K]^T (+ bias)
// A fp16 single; B fp16 hi/lo. 128x128 tile, K-chunk 64, 8 warps, 2 stages.
// ---------------------------------------------------------------------------
#define GKC 64
#define TILE_B 16384
#define STAGE_BYTES (3 * TILE_B)     // A, Bhi, Blo
#define GEMM_SMEM (2 * STAGE_BYTES + 1024)

__device__ __forceinline__ void load_tile(const __half* __restrict__ src,
                                          int rbase, int K, int k0,
                                          uint32_t tb, int tid) {
#pragma unroll
    for (int i = 0; i < 4; i++) {
        int idx = tid + i * 256;
        int r = idx >> 3;
        int c = idx & 7;
        const void* g = src + (size_t)(rbase + r) * K + k0 + c * 8;
        cpa16(tb + sw128((uint32_t)(r * 128 + c * 16)), g);
    }
}

template <bool BIAS>
__global__ __launch_bounds__(256) void gemm_mma(
    const __half* __restrict__ A,
    const __half* __restrict__ Bhi, const __half* __restrict__ Blo,
    const float* __restrict__ bias, float* __restrict__ Cout,
    int M, int N, int K)
{
    extern __shared__ char sm[];
    const uint32_t tiles = (smem_u32(sm) + 1023) & ~1023u;

    const int tid  = threadIdx.x;
    const int lane = tid & 31;
    const int wid  = tid >> 5;
    const int wm0  = (wid >> 2) * 64;
    const int wn0  = (wid & 3) * 32;
    const int bm = blockIdx.y * 128;
    const int bn = blockIdx.x * 128;

    const int lr = lane & 15;
    const int lc = (lane >> 4) << 4;

    float acc[4][4][4];
#pragma unroll
    for (int i = 0; i < 4; i++)
#pragma unroll
        for (int j = 0; j < 4; j++)
#pragma unroll
            for (int t = 0; t < 4; t++) acc[i][j][t] = 0.0f;

    const int NCH = K / GKC;

    {
        uint32_t st = tiles;
        load_tile(A,   bm, K, 0, st,              tid);
        load_tile(Bhi, bn, K, 0, st + TILE_B,     tid);
        load_tile(Blo, bn, K, 0, st + 2 * TILE_B, tid);
        cpa_commit();
    }

    for (int k = 0; k < NCH; k++) {
        const int b = k & 1;
        if (k + 1 < NCH) {
            const int nb = (k + 1) & 1;
            uint32_t st = tiles + nb * STAGE_BYTES;
            const int k0 = (k + 1) * GKC;
            load_tile(A,   bm, K, k0, st,              tid);
            load_tile(Bhi, bn, K, k0, st + TILE_B,     tid);
            load_tile(Blo, bn, K, k0, st + 2 * TILE_B, tid);
            cpa_commit();
            cpa_wait<1>();
        } else {
            cpa_wait<0>();
        }
        __syncthreads();

        const uint32_t st  = tiles + b * STAGE_BYTES;
        const uint32_t tA  = st;
        const uint32_t tBh = st + TILE_B;
        const uint32_t tBl = st + 2 * TILE_B;

#pragma unroll
        for (int kk = 0; kk < 4; kk++) {
            uint32_t af[4][4], bh[2][4], bl[2][4];
#pragma unroll
            for (int mt = 0; mt < 4; mt++) {
                uint32_t o = sw128((uint32_t)((wm0 + mt * 16 + lr) * 128 + kk * 32 + lc));
                ldsm_x4(af[mt], tA + o);
            }
#pragma unroll
            for (int ng = 0; ng < 2; ng++) {
                uint32_t o = sw128((uint32_t)((wn0 + ng * 16 + lr) * 128 + kk * 32 + lc));
                ldsm_x4(bh[ng], tBh + o);
                ldsm_x4(bl[ng], tBl + o);
            }
#pragma unroll
            for (int mt = 0; mt < 4; mt++)
#pragma unroll
                for (int nt = 0; nt < 4; nt++) {
                    const int ng = nt >> 1, s = nt & 1;
                    mma_fp16(acc[mt][nt], af[mt], bh[ng][s], bh[ng][2 + s]);
                    mma_fp16(acc[mt][nt], af[mt], bl[ng][s], bl[ng][2 + s]);
                }
        }
        __syncthreads();
    }

    const int gq = lane >> 2;
    const int tg = lane & 3;
#pragma unroll
    for (int mt = 0; mt < 4; mt++) {
        const int row0 = bm + wm0 + mt * 16 + gq;
#pragma unroll
        for (int nt = 0; nt < 4; nt++) {
            const int col = bn + wn0 + nt * 8 + tg * 2;
            float2 v0 = make_float2(acc[mt][nt][0], acc[mt][nt][1]);
            float2 v1 = make_float2(acc[mt][nt][2], acc[mt][nt][3]);
            if (BIAS) {
                float b0v = bias[col], b1v = bias[col + 1];
                v0.x += b0v; v0.y += b1v;
                v1.x += b0v; v1.y += b1v;
            }
            *(float2*)(Cout + (size_t)row0 * N + col)       = v0;
            *(float2*)(Cout + (size_t)(row0 + 8) * N + col) = v1;
        }
    }
}

// ---------------------------------------------------------------------------
// Flash attention via mma.sync fp16 2-term
// CTA: 128 queries x (b,h). 8 warps x 16 rows. KV tiles of 64, 2-stage cp.async.
// smem: Q 16KB + 2 stages x (Kh,Kl,Vth,Vtl 8KB each) = 80KB
// ---------------------------------------------------------------------------
#define AT_STAGE 32768
#define AT_SMEM (16384 + 2 * AT_STAGE + 1024)

__device__ __forceinline__ void at_load_kv(
    const __half* kh, const __half* kl,
    const __half* vth, const __half* vtl,
    int kv0, uint32_t st, int tid)
{
#pragma unroll
    for (int i = 0; i < 2; i++) {
        int idx = tid + i * 256;
        int r = idx >> 3;
        int c = idx & 7;
        uint32_t so = sw128((uint32_t)(r * 128 + c * 16));
        cpa16(st + so,           kh  + (size_t)(kv0 + r) * D_ + c * 8);
        cpa16(st + 8192 + so,    kl  + (size_t)(kv0 + r) * D_ + c * 8);
        cpa16(st + 16384 + so,   vth + (size_t)r * M_ + kv0 + c * 8);
        cpa16(st + 24576 + so,   vtl + (size_t)r * M_ + kv0 + c * 8);
    }
}

__global__ __launch_bounds__(256) void attn_mma(
    const __half* __restrict__ Qh,
    const __half* __restrict__ Kh, const __half* __restrict__ Kl,
    const __half* __restrict__ Vth, const __half* __restrict__ Vtl,
    __half* __restrict__ oh)
{
    extern __shared__ char sm[];
    const uint32_t base = (smem_u32(sm) + 1023) & ~1023u;
    const uint32_t sQ = base;
    const uint32_t sStage = base + 16384;

    const int tid  = threadIdx.x;
    const int lane = tid & 31;
    const int wid  = tid >> 5;
    const int qt = blockIdx.x;
    const int h  = blockIdx.y;
    const int b  = blockIdx.z;
    const int bh = b * H_ + h;

    const __half* qg  = Qh + ((size_t)bh * N_ + qt * 128) * D_;
    const __half* khg = Kh + (size_t)bh * M_ * D_;
    const __half* klg = Kl + (size_t)bh * M_ * D_;
    const __half* vhg = Vth + (size_t)bh * D_ * M_;
    const __half* vlg = Vtl + (size_t)bh * D_ * M_;

    // Q tile: 128 rows x 128 bytes = 16KB -> need full 1024 cpa16 indices
#pragma unroll
    for (int i = 0; i < 4; i++) {
        int idx = tid + i * 256;
        int r = idx >> 3;        // 0..127
        int c = idx & 7;
        uint32_t so = sw128((uint32_t)(r * 128 + c * 16));
        cpa16(sQ + so, qg + (size_t)r * D_ + c * 8);
    }
    at_load_kv(khg, klg, vhg, vlg, 0, sStage, tid);
    cpa_commit();

    const int lr = lane & 15;
    const int lc = (lane >> 4) << 4;
    const int w16 = wid * 16;

    uint32_t qf[4][4];
    float O[8][4];
#pragma unroll
    for (int nt = 0; nt < 8; nt++)
#pragma unroll
        for (int t = 0; t < 4; t++) O[nt][t] = 0.0f;
    float m0 = -1e30f, m1 = -1e30f, l0 = 0.0f, l1 = 0.0f;

    for (int kt = 0; kt < KVT; kt++) {
        const int bs = kt & 1;
        if (kt + 1 < KVT) {
            at_load_kv(khg, klg, vhg, vlg, (kt + 1) * 64,
                       sStage + ((kt + 1) & 1) * AT_STAGE, tid);
            cpa_commit();
            cpa_wait<1>();
        } else {
            cpa_wait<0>();
        }
        __syncthreads();

        if (kt == 0) {
#pragma unroll
            for (int kk = 0; kk < 4; kk++) {
                uint32_t o = sw128((uint32_t)((w16 + lr) * 128 + kk * 32 + lc));
                ldsm_x4(qf[kk], sQ + o);
            }
        }

        const uint32_t tK  = sStage + bs * AT_STAGE;
        const uint32_t tKl = tK + 8192;
        const uint32_t tV  = tK + 16384;
        const uint32_t tVl = tK + 24576;

        // ---- S = Q . K^T (2-term) ----
        float S[8][4];
#pragma unroll
        for (int nt = 0; nt < 8; nt++)
#pragma unroll
            for (int t = 0; t < 4; t++) S[nt][t] = 0.0f;

#pragma unroll
        for (int kk = 0; kk < 4; kk++) {
            uint32_t bhf[4][4], blf[4][4];
#pragma unroll
            for (int ng = 0; ng < 4; ng++) {
                uint32_t o = sw128((uint32_t)((ng * 16 + lr) * 128 + kk * 32 + lc));
                ldsm_x4(bhf[ng], tK + o);
                ldsm_x4(blf[ng], tKl + o);
            }
#pragma unroll
            for (int ng = 0; ng < 4; ng++)
#pragma unroll
                for (int s = 0; s < 2; s++) {
                    const int nt = ng * 2 + s;
                    mma_fp16(S[nt], qf[kk], bhf[ng][s], bhf[ng][2 + s]);
                    mma_fp16(S[nt], qf[kk], blf[ng][s], blf[ng][2 + s]);
                }
        }

        // ---- online softmax ----
        float mt0 = -1e30f, mt1 = -1e30f;
#pragma unroll
        for (int nt = 0; nt < 8; nt++) {
            mt0 = fmaxf(mt0, fmaxf(S[nt][0], S[nt][1]));
            mt1 = fmaxf(mt1, fmaxf(S[nt][2], S[nt][3]));
        }
        mt0 = fmaxf(mt0, __shfl_xor_sync(0xffffffffu, mt0, 1));
        mt0 = fmaxf(mt0, __shfl_xor_sync(0xffffffffu, mt0, 2));
        mt1 = fmaxf(mt1, __shfl_xor_sync(0xffffffffu, mt1, 1));
        mt1 = fmaxf(mt1, __shfl_xor_sync(0xffffffffu, mt1, 2));

        float mn0 = fmaxf(m0, mt0), mn1 = fmaxf(m1, mt1);
        float a0 = __expf(m0 - mn0), a1 = __expf(m1 - mn1);
        m0 = mn0; m1 = mn1;

        float rs0 = 0.0f, rs1 = 0.0f;
#pragma unroll
        for (int nt = 0; nt < 8; nt++) {
            S[nt][0] = __expf(S[nt][0] - m0);
            S[nt][1] = __expf(S[nt][1] - m0);
            S[nt][2] = __expf(S[nt][2] - m1);
            S[nt][3] = __expf(S[nt][3] - m1);
            rs0 += S[nt][0] + S[nt][1];
            rs1 += S[nt][2] + S[nt][3];
        }
        rs0 += __shfl_xor_sync(0xffffffffu, rs0, 1);
        rs0 += __shfl_xor_sync(0xffffffffu, rs0, 2);
        rs1 += __shfl_xor_sync(0xffffffffu, rs1, 1);
        rs1 += __shfl_xor_sync(0xffffffffu, rs1, 2);
        l0 = l0 * a0 + rs0;
        l1 = l1 * a1 + rs1;

#pragma unroll
        for (int nt = 0; nt < 8; nt++) {
            O[nt][0] *= a0; O[nt][1] *= a0;
            O[nt][2] *= a1; O[nt][3] *= a1;
        }

        // ---- pack P fp16 A-fragments ----
        uint32_t ph[4][4];
#pragma unroll
        for (int j = 0; j < 4; j++) {
            ph[j][0] = pack_h2(S[2 * j][0],     S[2 * j][1]);
            ph[j][1] = pack_h2(S[2 * j][2],     S[2 * j][3]);
            ph[j][2] = pack_h2(S[2 * j + 1][0], S[2 * j + 1][1]);
            ph[j][3] = pack_h2(S[2 * j + 1][2], S[2 * j + 1][3]);
        }

        // ---- O += P . Vt^T (2-term) ----
#pragma unroll
        for (int j = 0; j < 4; j++) {
            uint32_t vhf[4][4], vlf[4][4];
#pragma unroll
            for (int ng = 0; ng < 4; ng++) {
                uint32_t o = sw128((uint32_t)((ng * 16 + lr) * 128 + j * 32 + lc));
                ldsm_x4(vhf[ng], tV + o);
                ldsm_x4(vlf[ng], tVl + o);
            }
#pragma unroll
            for (int ng = 0; ng < 4; ng++)
#pragma unroll
                for (int s = 0; s < 2; s++) {
                    const int nt = ng * 2 + s;
                    mma_fp16(O[nt], ph[j], vhf[ng][s], vhf[ng][2 + s]);
                    mma_fp16(O[nt], ph[j], vlf[ng][s], vlf[ng][2 + s]);
                }
        }
        __syncthreads();
    }

    // ---- epilogue: O/l -> fp16 single at (b, n, h*64 + d) ----
    const float inv0 = 1.0f / l0, inv1 = 1.0f / l1;
    const int g  = lane >> 2;
    const int tg = lane & 3;
    const int n0 = qt * 128 + w16 + g;
#pragma unroll
    for (int nt = 0; nt < 8; nt++) {
        const int col = h * D_ + nt * 8 + tg * 2;
        {
            size_t o = (size_t)(b * N_ + n0) * C_ + col;
            *(uint32_t*)(oh + o) = pack_h2(O[nt][0] * inv0, O[nt][1] * inv0);
        }
        {
            size_t o = (size_t)(b * N_ + n0 + 8) * C_ + col;
            *(uint32_t*)(oh + o) = pack_h2(O[nt][2] * inv1, O[nt][3] * inv1);
        }
    }
}

// ---------------------------------------------------------------------------
extern "C" void kernel_launch(void* const* d_in, const int* in_sizes, int n_in,
                              void* d_out, int out_size) {
    const float* x      = (const float*)d_in[0];
    const float* ctx    = (const float*)d_in[1];
    const float* w_qkv  = (const float*)d_in[2];
    const float* w_proj = (const float*)d_in[3];
    const float* b_proj = (const float*)d_in[4];
    float* out = (float*)d_out;

    void *p;
    cudaGetSymbolAddress(&p, g_qkv);      float* qkvp = (float*)p;
    cudaGetSymbolAddress(&p, g_xh);       __half* xh  = (__half*)p;
    cudaGetSymbolAddress(&p, g_wqkv_hi);  __half* wqh = (__half*)p;
    cudaGetSymbolAddress(&p, g_wqkv_lo);  __half* wql = (__half*)p;
    cudaGetSymbolAddress(&p, g_wproj_hi); __half* wph = (__half*)p;
    cudaGetSymbolAddress(&p, g_wproj_lo); __half* wpl = (__half*)p;
    cudaGetSymbolAddress(&p, g_ah);       __half* ah  = (__half*)p;
    cudaGetSymbolAddress(&p, g_qh);       __half* qh  = (__half*)p;
    cudaGetSymbolAddress(&p, g_kh);       __half* kh  = (__half*)p;
    cudaGetSymbolAddress(&p, g_kl);       __half* kl  = (__half*)p;
    cudaGetSymbolAddress(&p, g_vth);      __half* vth = (__half*)p;
    cudaGetSymbolAddress(&p, g_vtl);      __half* vtl = (__half*)p;

    cudaFuncSetAttribute(gemm_mma<false>, cudaFuncAttributeMaxDynamicSharedMemorySize, GEMM_SMEM);
    cudaFuncSetAttribute(gemm_mma<true>,  cudaFuncAttributeMaxDynamicSharedMemorySize, GEMM_SMEM);
    cudaFuncSetAttribute(attn_mma,        cudaFuncAttributeMaxDynamicSharedMemorySize, AT_SMEM);

    // 0) decompose inputs/weights
    {
        int n4x = B_ * N_ * C_ / 4;
        int n4q = 3 * C_ * C_ / 4;
        int n4p = C_ * C_ / 4;
        decomp_h<<<(n4x + 255) / 256, 256>>>(x, xh, n4x);
        decomp_hl<<<(n4q + 255) / 256, 256>>>(w_qkv, wqh, wql, n4q);
        decomp_hl<<<(n4p + 255) / 256, 256>>>(w_proj, wph, wpl, n4p);
    }

    // 1) QKV projection
    {
        dim3 grid(3 * C_ / 128, B_ * N_ / 128);
        gemm_mma<false><<<grid, 256, GEMM_SMEM>>>(xh, wqh, wql, nullptr, qkvp,
                                                  B_ * N_, 3 * C_, C_);
    }

    // 1.5) attention operand prep
    {
        prepq_kernel<<<4096, 256>>>(qkvp, qh);
        dim3 grid(KVT, B_ * H_);
        prepkv_kernel<<<grid, 256>>>(qkvp, ctx, kh, kl, vth, vtl);
    }

    // 2) Attention via mma.sync
    {
        dim3 grid(N_ / 128, H_, B_);
        attn_mma<<<grid, 256, AT_SMEM>>>(qh, kh, kl, vth, vtl, ah);
    }

    // 3) Output projection with bias
    {
        dim3 grid(C_ / 128, B_ * N_ / 128);
        gemm_mma<true><<<grid, 256, GEMM_SMEM>>>(ah, wph, wpl, b_proj, out,
                                                 B_ * N_, C_, C_);
    }
}

// round 7
// speedup vs baseline: 7.3966x; 1.6819x over previous
#include <cuda_runtime.h>
#include <cuda_fp16.h>
#include <cstdint>
#include <math.h>

// Problem constants (fixed by setup_inputs)
#define B_   4
#define N_   1024
#define C_   1024
#define H_   16
#define D_   64
#define NC_  256
#define M_   1280            // NC_ + N_
#define KVT  20              // M_/64 kv tiles

// ---------------------------------------------------------------------------
// Scratch (allocation-free rule: __device__ globals)
// ---------------------------------------------------------------------------
__device__ __half g_qkvh[(size_t)B_ * N_ * 3 * C_];           // GEMM1 out, fp16
__device__ __half g_xh[(size_t)B_ * N_ * C_];                 // x fp16
__device__ __half g_wqkv[(size_t)3 * C_ * C_];
__device__ __half g_wproj[(size_t)C_ * C_];
__device__ __half g_ah[(size_t)B_ * N_ * C_];                 // attn out fp16
// attention operand buffers (per bh = b*H+h)
__device__ __half g_qh[(size_t)B_ * H_ * N_ * D_];            // Q fp16 (scaled)
__device__ __half g_kh[(size_t)B_ * H_ * M_ * D_];
__device__ __half g_vth[(size_t)B_ * H_ * D_ * M_];           // V^T [d][kv]

// ---------------------------------------------------------------------------
// Helpers (sm_100 baseline PTX only)
// ---------------------------------------------------------------------------
__device__ __forceinline__ uint32_t smem_u32(const void* p) {
    uint32_t a;
    asm("{ .reg .u64 t; cvta.to.shared.u64 t, %1; cvt.u32.u64 %0, t; }" : "=r"(a) : "l"(p));
    return a;
}
__device__ __forceinline__ void cpa16(uint32_t d, const void* g) {
    asm volatile("cp.async.cg.shared.global [%0], [%1], 16;" :: "r"(d), "l"(g));
}
__device__ __forceinline__ void cpa_commit() { asm volatile("cp.async.commit_group;"); }
template <int n> __device__ __forceinline__ void cpa_wait() {
    asm volatile("cp.async.wait_group %0;" :: "n"(n));
}
__device__ __forceinline__ uint32_t sw128(uint32_t off) { return off ^ ((off >> 3) & 0x70); }

__device__ __forceinline__ void ldsm_x4(uint32_t* r, uint32_t addr) {
    asm volatile("ldmatrix.sync.aligned.m8n8.x4.shared.b16 {%0,%1,%2,%3}, [%4];"
        : "=r"(r[0]), "=r"(r[1]), "=r"(r[2]), "=r"(r[3]) : "r"(addr));
}
__device__ __forceinline__ void mma_fp16(float* d, const uint32_t* a,
                                         uint32_t b0, uint32_t b1) {
    asm volatile(
        "mma.sync.aligned.m16n8k16.row.col.f32.f16.f16.f32 "
        "{%0,%1,%2,%3},{%4,%5,%6,%7},{%8,%9},{%0,%1,%2,%3};"
        : "+f"(d[0]), "+f"(d[1]), "+f"(d[2]), "+f"(d[3])
        : "r"(a[0]), "r"(a[1]), "r"(a[2]), "r"(a[3]), "r"(b0), "r"(b1));
}
__device__ __forceinline__ uint32_t pack_h2(float a, float b) {
    __half2 t = __floats2half2_rn(a, b);
    return *(uint32_t*)&t;
}

// ---------------------------------------------------------------------------
// fp32 -> fp16 conversion
// ---------------------------------------------------------------------------
__global__ void decomp_h(const float* __restrict__ in, __half* __restrict__ o, int n4) {
    int i = blockIdx.x * blockDim.x + threadIdx.x;
    if (i >= n4) return;
    float4 v = ((const float4*)in)[i];
    ((uint32_t*)o)[i * 2 + 0] = pack_h2(v.x, v.y);
    ((uint32_t*)o)[i * 2 + 1] = pack_h2(v.z, v.w);
}

// ---------------------------------------------------------------------------
// Prep: Q fp16 (scale folded), layout [bh][n][d]; source = fp16 qkv slot 0
// ---------------------------------------------------------------------------
__global__ void prepq_kernel(const __half* __restrict__ qkv, __half* __restrict__ qh) {
    int t = blockIdx.x * blockDim.x + threadIdx.x;   // 1M threads, 4 halves each
    int d4 = t & 15;
    int h  = (t >> 4) & 15;
    int n  = (t >> 8) & 1023;
    int b  = t >> 18;
    const __half* src = qkv + (((size_t)(b * N_ + n)) * 3 + 0) * C_ + h * D_ + d4 * 4;
    __half2 v0 = *(const __half2*)src;
    __half2 v1 = *(const __half2*)(src + 2);
    const __half2 s = __floats2half2_rn(0.125f, 0.125f);   // exact power of 2
    v0 = __hmul2(v0, s);
    v1 = __hmul2(v1, s);
    size_t o = (((size_t)(b * H_ + h)) * N_ + n) * D_ + d4 * 4;
    *(__half2*)(qh + o)     = v0;
    *(__half2*)(qh + o + 2) = v1;
}

// ---------------------------------------------------------------------------
// Prep: K fp16 [bh][M][D] + Vt fp16 [bh][D][M]; sources: ctx fp32 / qkv fp16
// ---------------------------------------------------------------------------
__global__ void prepkv_kernel(const __half* __restrict__ qkv, const float* __restrict__ ctx,
                              __half* __restrict__ kh, __half* __restrict__ vth) {
    __shared__ float sv[64][65];
    const int tid = threadIdx.x;
    const int kv0 = blockIdx.x * 64;
    const int bh  = blockIdx.y;
    const int b = bh >> 4, h = bh & 15;

#pragma unroll
    for (int it = 0; it < 4; it++) {
        int idx = tid + it * 256;
        int r  = idx >> 4;          // kv row 0..63
        int dc = idx & 15;          // d chunk of 4
        int kv = kv0 + r;
        float kx[4], vx[4];
        if (kv < NC_) {
            const float* base = ctx + (((size_t)(b * NC_ + kv)) * 2 + 0) * C_ + h * D_ + dc * 4;
            float4 kvec = *(const float4*)base;
            float4 vvec = *(const float4*)(base + C_);
            kx[0] = kvec.x; kx[1] = kvec.y; kx[2] = kvec.z; kx[3] = kvec.w;
            vx[0] = vvec.x; vx[1] = vvec.y; vx[2] = vvec.z; vx[3] = vvec.w;
        } else {
            const __half* base = qkv + (((size_t)(b * N_ + kv - NC_)) * 3 + 1) * C_ + h * D_ + dc * 4;
            __half2 k0 = *(const __half2*)base, k1 = *(const __half2*)(base + 2);
            __half2 w0 = *(const __half2*)(base + C_), w1 = *(const __half2*)(base + C_ + 2);
            kx[0] = __low2float(k0); kx[1] = __high2float(k0);
            kx[2] = __low2float(k1); kx[3] = __high2float(k1);
            vx[0] = __low2float(w0); vx[1] = __high2float(w0);
            vx[2] = __low2float(w1); vx[3] = __high2float(w1);
        }
        size_t o = (((size_t)bh) * M_ + kv) * D_ + dc * 4;
        *(uint32_t*)(kh + o)     = pack_h2(kx[0], kx[1]);
        *(uint32_t*)(kh + o + 2) = pack_h2(kx[2], kx[3]);
        sv[r][dc * 4 + 0] = vx[0]; sv[r][dc * 4 + 1] = vx[1];
        sv[r][dc * 4 + 2] = vx[2]; sv[r][dc * 4 + 3] = vx[3];
    }
    __syncthreads();

    {
        int d  = tid >> 2;
        int q4 = (tid & 3) * 16;
        size_t o = ((size_t)bh) * D_ * M_ + (size_t)d * M_ + kv0 + q4;
#pragma unroll
        for (int k2 = 0; k2 < 8; k2++) {
            *(uint32_t*)(vth + o + k2 * 2) =
                pack_h2(sv[q4 + k2 * 2][d], sv[q4 + k2 * 2 + 1][d]);
        }
    }
}

// ---------------------------------------------------------------------------
// mma.sync fp16 GEMM: C[M,N] = A[M,K] @ B[N,K]^T (+ bias)
// 128x128 tile, K-chunk 64, 8 warps (2x4), 2-stage cp.async, 2 CTAs/SM.
// ---------------------------------------------------------------------------
#define GKC 64
#define TILE_B 16384
#define STAGE_BYTES (2 * TILE_B)     // A, B
#define GEMM_SMEM (2 * STAGE_BYTES + 1024)

__device__ __forceinline__ void load_tile(const __half* __restrict__ src,
                                          int rbase, int K, int k0,
                                          uint32_t tb, int tid) {
#pragma unroll
    for (int i = 0; i < 4; i++) {
        int idx = tid + i * 256;
        int r = idx >> 3;
        int c = idx & 7;
        const void* g = src + (size_t)(rbase + r) * K + k0 + c * 8;
        cpa16(tb + sw128((uint32_t)(r * 128 + c * 16)), g);
    }
}

template <bool OUTHALF>
__global__ __launch_bounds__(256, 2) void gemm_mma(
    const __half* __restrict__ A, const __half* __restrict__ Bm,
    const float* __restrict__ bias,
    float* __restrict__ Cf, __half* __restrict__ Ch,
    int M, int N, int K)
{
    extern __shared__ char sm[];
    const uint32_t tiles = (smem_u32(sm) + 1023) & ~1023u;

    const int tid  = threadIdx.x;
    const int lane = tid & 31;
    const int wid  = tid >> 5;
    const int wm0  = (wid >> 2) * 64;
    const int wn0  = (wid & 3) * 32;
    const int bm = blockIdx.y * 128;
    const int bn = blockIdx.x * 128;

    const int lr = lane & 15;
    const int lc = (lane >> 4) << 4;

    float acc[4][4][4];
#pragma unroll
    for (int i = 0; i < 4; i++)
#pragma unroll
        for (int j = 0; j < 4; j++)
#pragma unroll
            for (int t = 0; t < 4; t++) acc[i][j][t] = 0.0f;

    const int NCH = K / GKC;

    {
        load_tile(A,  bm, K, 0, tiles,          tid);
        load_tile(Bm, bn, K, 0, tiles + TILE_B, tid);
        cpa_commit();
    }

    for (int k = 0; k < NCH; k++) {
        const int b = k & 1;
        if (k + 1 < NCH) {
            uint32_t st = tiles + ((k + 1) & 1) * STAGE_BYTES;
            const int k0 = (k + 1) * GKC;
            load_tile(A,  bm, K, k0, st,          tid);
            load_tile(Bm, bn, K, k0, st + TILE_B, tid);
            cpa_commit();
            cpa_wait<1>();
        } else {
            cpa_wait<0>();
        }
        __syncthreads();

        const uint32_t tA = tiles + b * STAGE_BYTES;
        const uint32_t tB = tA + TILE_B;

#pragma unroll
        for (int kk = 0; kk < 4; kk++) {
            uint32_t af[4][4], bf[2][4];
#pragma unroll
            for (int mt = 0; mt < 4; mt++) {
                uint32_t o = sw128((uint32_t)((wm0 + mt * 16 + lr) * 128 + kk * 32 + lc));
                ldsm_x4(af[mt], tA + o);
            }
#pragma unroll
            for (int ng = 0; ng < 2; ng++) {
                uint32_t o = sw128((uint32_t)((wn0 + ng * 16 + lr) * 128 + kk * 32 + lc));
                ldsm_x4(bf[ng], tB + o);
            }
#pragma unroll
            for (int mt = 0; mt < 4; mt++)
#pragma unroll
                for (int nt = 0; nt < 4; nt++) {
                    const int ng = nt >> 1, s = nt & 1;
                    mma_fp16(acc[mt][nt], af[mt], bf[ng][s], bf[ng][2 + s]);
                }
        }
        __syncthreads();
    }

    const int gq = lane >> 2;
    const int tg = lane & 3;
#pragma unroll
    for (int mt = 0; mt < 4; mt++) {
        const int row0 = bm + wm0 + mt * 16 + gq;
#pragma unroll
        for (int nt = 0; nt < 4; nt++) {
            const int col = bn + wn0 + nt * 8 + tg * 2;
            if (OUTHALF) {
                *(uint32_t*)(Ch + (size_t)row0 * N + col) =
                    pack_h2(acc[mt][nt][0], acc[mt][nt][1]);
                *(uint32_t*)(Ch + (size_t)(row0 + 8) * N + col) =
                    pack_h2(acc[mt][nt][2], acc[mt][nt][3]);
            } else {
                float b0v = bias[col], b1v = bias[col + 1];
                float2 v0 = make_float2(acc[mt][nt][0] + b0v, acc[mt][nt][1] + b1v);
                float2 v1 = make_float2(acc[mt][nt][2] + b0v, acc[mt][nt][3] + b1v);
                *(float2*)(Cf + (size_t)row0 * N + col)       = v0;
                *(float2*)(Cf + (size_t)(row0 + 8) * N + col) = v1;
            }
        }
    }
}

// ---------------------------------------------------------------------------
// Flash attention via mma.sync, pure fp16 operands
// CTA: 128 queries x (b,h). 8 warps x 16 rows. KV tiles of 64, 2-stage cp.async.
// smem: Q 16KB + 2 stages x (K 8KB + Vt 8KB) = 48KB
// ---------------------------------------------------------------------------
#define AT_STAGE 16384
#define AT_SMEM (16384 + 2 * AT_STAGE + 1024)

__device__ __forceinline__ void at_load_kv(
    const __half* kh, const __half* vth, int kv0, uint32_t st, int tid)
{
#pragma unroll
    for (int i = 0; i < 2; i++) {
        int idx = tid + i * 256;
        int r = idx >> 3;        // 0..63
        int c = idx & 7;
        uint32_t so = sw128((uint32_t)(r * 128 + c * 16));
        cpa16(st + so,        kh  + (size_t)(kv0 + r) * D_ + c * 8);
        cpa16(st + 8192 + so, vth + (size_t)r * M_ + kv0 + c * 8);
    }
}

__global__ __launch_bounds__(256) void attn_mma(
    const __half* __restrict__ Qh, const __half* __restrict__ Kh,
    const __half* __restrict__ Vth, __half* __restrict__ oh)
{
    extern __shared__ char sm[];
    const uint32_t base = (smem_u32(sm) + 1023) & ~1023u;
    const uint32_t sQ = base;
    const uint32_t sStage = base + 16384;

    const int tid  = threadIdx.x;
    const int lane = tid & 31;
    const int wid  = tid >> 5;
    const int qt = blockIdx.x;
    const int h  = blockIdx.y;
    const int b  = blockIdx.z;
    const int bh = b * H_ + h;

    const __half* qg  = Qh + ((size_t)bh * N_ + qt * 128) * D_;
    const __half* khg = Kh + (size_t)bh * M_ * D_;
    const __half* vhg = Vth + (size_t)bh * D_ * M_;

    // Q tile: 128 rows x 128 bytes
#pragma unroll
    for (int i = 0; i < 4; i++) {
        int idx = tid + i * 256;
        int r = idx >> 3;        // 0..127
        int c = idx & 7;
        cpa16(sQ + sw128((uint32_t)(r * 128 + c * 16)), qg + (size_t)r * D_ + c * 8);
    }
    at_load_kv(khg, vhg, 0, sStage, tid);
    cpa_commit();

    const int lr = lane & 15;
    const int lc = (lane >> 4) << 4;
    const int w16 = wid * 16;

    uint32_t qf[4][4];
    float O[8][4];
#pragma unroll
    for (int nt = 0; nt < 8; nt++)
#pragma unroll
        for (int t = 0; t < 4; t++) O[nt][t] = 0.0f;
    float m0 = -1e30f, m1 = -1e30f, l0 = 0.0f, l1 = 0.0f;

    for (int kt = 0; kt < KVT; kt++) {
        const int bs = kt & 1;
        if (kt + 1 < KVT) {
            at_load_kv(khg, vhg, (kt + 1) * 64, sStage + ((kt + 1) & 1) * AT_STAGE, tid);
            cpa_commit();
            cpa_wait<1>();
        } else {
            cpa_wait<0>();
        }
        __syncthreads();

        if (kt == 0) {
#pragma unroll
            for (int kk = 0; kk < 4; kk++) {
                uint32_t o = sw128((uint32_t)((w16 + lr) * 128 + kk * 32 + lc));
                ldsm_x4(qf[kk], sQ + o);
            }
        }

        const uint32_t tK = sStage + bs * AT_STAGE;
        const uint32_t tV = tK + 8192;

        // ---- S = Q . K^T ----
        float S[8][4];
#pragma unroll
        for (int nt = 0; nt < 8; nt++)
#pragma unroll
            for (int t = 0; t < 4; t++) S[nt][t] = 0.0f;

#pragma unroll
        for (int kk = 0; kk < 4; kk++) {
            uint32_t bf[4][4];
#pragma unroll
            for (int ng = 0; ng < 4; ng++) {
                uint32_t o = sw128((uint32_t)((ng * 16 + lr) * 128 + kk * 32 + lc));
                ldsm_x4(bf[ng], tK + o);
            }
#pragma unroll
            for (int ng = 0; ng < 4; ng++)
#pragma unroll
                for (int s = 0; s < 2; s++)
                    mma_fp16(S[ng * 2 + s], qf[kk], bf[ng][s], bf[ng][2 + s]);
        }

        // ---- online softmax ----
        float mt0 = -1e30f, mt1 = -1e30f;
#pragma unroll
        for (int nt = 0; nt < 8; nt++) {
            mt0 = fmaxf(mt0, fmaxf(S[nt][0], S[nt][1]));
            mt1 = fmaxf(mt1, fmaxf(S[nt][2], S[nt][3]));
        }
        mt0 = fmaxf(mt0, __shfl_xor_sync(0xffffffffu, mt0, 1));
        mt0 = fmaxf(mt0, __shfl_xor_sync(0xffffffffu, mt0, 2));
        mt1 = fmaxf(mt1, __shfl_xor_sync(0xffffffffu, mt1, 1));
        mt1 = fmaxf(mt1, __shfl_xor_sync(0xffffffffu, mt1, 2));

        float mn0 = fmaxf(m0, mt0), mn1 = fmaxf(m1, mt1);
        float a0 = __expf(m0 - mn0), a1 = __expf(m1 - mn1);
        m0 = mn0; m1 = mn1;

        float rs0 = 0.0f, rs1 = 0.0f;
#pragma unroll
        for (int nt = 0; nt < 8; nt++) {
            S[nt][0] = __expf(S[nt][0] - m0);
            S[nt][1] = __expf(S[nt][1] - m0);
            S[nt][2] = __expf(S[nt][2] - m1);
            S[nt][3] = __expf(S[nt][3] - m1);
            rs0 += S[nt][0] + S[nt][1];
            rs1 += S[nt][2] + S[nt][3];
        }
        rs0 += __shfl_xor_sync(0xffffffffu, rs0, 1);
        rs0 += __shfl_xor_sync(0xffffffffu, rs0, 2);
        rs1 += __shfl_xor_sync(0xffffffffu, rs1, 1);
        rs1 += __shfl_xor_sync(0xffffffffu, rs1, 2);
        l0 = l0 * a0 + rs0;
        l1 = l1 * a1 + rs1;

#pragma unroll
        for (int nt = 0; nt < 8; nt++) {
            O[nt][0] *= a0; O[nt][1] *= a0;
            O[nt][2] *= a1; O[nt][3] *= a1;
        }

        // ---- pack P fp16 A-fragments ----
        uint32_t ph[4][4];
#pragma unroll
        for (int j = 0; j < 4; j++) {
            ph[j][0] = pack_h2(S[2 * j][0],     S[2 * j][1]);
            ph[j][1] = pack_h2(S[2 * j][2],     S[2 * j][3]);
            ph[j][2] = pack_h2(S[2 * j + 1][0], S[2 * j + 1][1]);
            ph[j][3] = pack_h2(S[2 * j + 1][2], S[2 * j + 1][3]);
        }

        // ---- O += P . Vt^T ----
#pragma unroll
        for (int j = 0; j < 4; j++) {
            uint32_t vf[4][4];
#pragma unroll
            for (int ng = 0; ng < 4; ng++) {
                uint32_t o = sw128((uint32_t)((ng * 16 + lr) * 128 + j * 32 + lc));
                ldsm_x4(vf[ng], tV + o);
            }
#pragma unroll
            for (int ng = 0; ng < 4; ng++)
#pragma unroll
                for (int s = 0; s < 2; s++)
                    mma_fp16(O[ng * 2 + s], ph[j], vf[ng][s], vf[ng][2 + s]);
        }
        __syncthreads();
    }

    // ---- epilogue: O/l -> fp16 at (b, n, h*64 + d) ----
    const float inv0 = 1.0f / l0, inv1 = 1.0f / l1;
    const int g  = lane >> 2;
    const int tg = lane & 3;
    const int n0 = qt * 128 + w16 + g;
#pragma unroll
    for (int nt = 0; nt < 8; nt++) {
        const int col = h * D_ + nt * 8 + tg * 2;
        *(uint32_t*)(oh + (size_t)(b * N_ + n0) * C_ + col) =
            pack_h2(O[nt][0] * inv0, O[nt][1] * inv0);
        *(uint32_t*)(oh + (size_t)(b * N_ + n0 + 8) * C_ + col) =
            pack_h2(O[nt][2] * inv1, O[nt][3] * inv1);
    }
}

// ---------------------------------------------------------------------------
extern "C" void kernel_launch(void* const* d_in, const int* in_sizes, int n_in,
                              void* d_out, int out_size) {
    const float* x      = (const float*)d_in[0];
    const float* ctx    = (const float*)d_in[1];
    const float* w_qkv  = (const float*)d_in[2];
    const float* w_proj = (const float*)d_in[3];
    const float* b_proj = (const float*)d_in[4];
    float* out = (float*)d_out;

    void *p;
    cudaGetSymbolAddress(&p, g_qkvh);  __half* qkvh = (__half*)p;
    cudaGetSymbolAddress(&p, g_xh);    __half* xh   = (__half*)p;
    cudaGetSymbolAddress(&p, g_wqkv);  __half* wq   = (__half*)p;
    cudaGetSymbolAddress(&p, g_wproj); __half* wp   = (__half*)p;
    cudaGetSymbolAddress(&p, g_ah);    __half* ah   = (__half*)p;
    cudaGetSymbolAddress(&p, g_qh);    __half* qh   = (__half*)p;
    cudaGetSymbolAddress(&p, g_kh);    __half* kh   = (__half*)p;
    cudaGetSymbolAddress(&p, g_vth);   __half* vth  = (__half*)p;

    cudaFuncSetAttribute(gemm_mma<true>,  cudaFuncAttributeMaxDynamicSharedMemorySize, GEMM_SMEM);
    cudaFuncSetAttribute(gemm_mma<false>, cudaFuncAttributeMaxDynamicSharedMemorySize, GEMM_SMEM);
    cudaFuncSetAttribute(attn_mma,        cudaFuncAttributeMaxDynamicSharedMemorySize, AT_SMEM);

    // 0) convert inputs/weights to fp16
    {
        int n4x = B_ * N_ * C_ / 4;
        int n4q = 3 * C_ * C_ / 4;
        int n4p = C_ * C_ / 4;
        decomp_h<<<(n4x + 255) / 256, 256>>>(x, xh, n4x);
        decomp_h<<<(n4q + 255) / 256, 256>>>(w_qkv, wq, n4q);
        decomp_h<<<(n4p + 255) / 256, 256>>>(w_proj, wp, n4p);
    }

    // 1) QKV projection -> fp16 qkv
    {
        dim3 grid(3 * C_ / 128, B_ * N_ / 128);
        gemm_mma<true><<<grid, 256, GEMM_SMEM>>>(xh, wq, nullptr, nullptr, qkvh,
                                                 B_ * N_, 3 * C_, C_);
    }

    // 1.5) attention operand prep
    {
        prepq_kernel<<<4096, 256>>>(qkvh, qh);
        dim3 grid(KVT, B_ * H_);
        prepkv_kernel<<<grid, 256>>>(qkvh, ctx, kh, vth);
    }

    // 2) Attention
    {
        dim3 grid(N_ / 128, H_, B_);
        attn_mma<<<grid, 256, AT_SMEM>>>(qh, kh, vth, ah);
    }

    // 3) Output projection with bias -> fp32 out
    {
        dim3 grid(C_ / 128, B_ * N_ / 128);
        gemm_mma<false><<<grid, 256, GEMM_SMEM>>>(ah, wp, b_proj, out, nullptr,
                                                  B_ * N_, C_, C_);
    }
}

// round 8
// speedup vs baseline: 8.0019x; 1.0818x over previous
#include <cuda_runtime.h>
#include <cuda_fp16.h>
#include <cstdint>
#include <math.h>

// Problem constants (fixed by setup_inputs)
#define B_   4
#define N_   1024
#define C_   1024
#define H_   16
#define D_   64
#define NC_  256
#define M_   1280            // NC_ + N_
#define KVT  20              // M_/64 kv tiles

// ---------------------------------------------------------------------------
// Scratch (allocation-free rule: __device__ globals)
// ---------------------------------------------------------------------------
__device__ __half g_qkvh[(size_t)B_ * N_ * 3 * C_];           // GEMM1 out, fp16 (Q pre-scaled)
__device__ __half g_xh[(size_t)B_ * N_ * C_];                 // x fp16
__device__ __half g_wqkv[(size_t)3 * C_ * C_];                // Q-rows pre-scaled by 0.125
__device__ __half g_wproj[(size_t)C_ * C_];
__device__ __half g_ah[(size_t)B_ * N_ * C_];                 // attn out fp16
__device__ __half g_kh[(size_t)B_ * H_ * M_ * D_];
__device__ __half g_vth[(size_t)B_ * H_ * D_ * M_];           // V^T [d][kv]

// ---------------------------------------------------------------------------
// Helpers (sm_100 baseline PTX only)
// ---------------------------------------------------------------------------
__device__ __forceinline__ uint32_t smem_u32(const void* p) {
    uint32_t a;
    asm("{ .reg .u64 t; cvta.to.shared.u64 t, %1; cvt.u32.u64 %0, t; }" : "=r"(a) : "l"(p));
    return a;
}
__device__ __forceinline__ void cpa16(uint32_t d, const void* g) {
    asm volatile("cp.async.cg.shared.global [%0], [%1], 16;" :: "r"(d), "l"(g));
}
__device__ __forceinline__ void cpa_commit() { asm volatile("cp.async.commit_group;"); }
template <int n> __device__ __forceinline__ void cpa_wait() {
    asm volatile("cp.async.wait_group %0;" :: "n"(n));
}
__device__ __forceinline__ uint32_t sw128(uint32_t off) { return off ^ ((off >> 3) & 0x70); }

__device__ __forceinline__ void ldsm_x4(uint32_t* r, uint32_t addr) {
    asm volatile("ldmatrix.sync.aligned.m8n8.x4.shared.b16 {%0,%1,%2,%3}, [%4];"
        : "=r"(r[0]), "=r"(r[1]), "=r"(r[2]), "=r"(r[3]) : "r"(addr));
}
__device__ __forceinline__ void mma_fp16(float* d, const uint32_t* a,
                                         uint32_t b0, uint32_t b1) {
    asm volatile(
        "mma.sync.aligned.m16n8k16.row.col.f32.f16.f16.f32 "
        "{%0,%1,%2,%3},{%4,%5,%6,%7},{%8,%9},{%0,%1,%2,%3};"
        : "+f"(d[0]), "+f"(d[1]), "+f"(d[2]), "+f"(d[3])
        : "r"(a[0]), "r"(a[1]), "r"(a[2]), "r"(a[3]), "r"(b0), "r"(b1));
}
__device__ __forceinline__ uint32_t pack_h2(float a, float b) {
    __half2 t = __floats2half2_rn(a, b);
    return *(uint32_t*)&t;
}

// ---------------------------------------------------------------------------
// One-shot fp32 -> fp16 conversion of x, w_qkv (Q rows scaled), w_proj
// ---------------------------------------------------------------------------
#define N4X (B_ * N_ * C_ / 4)       // 1048576
#define N4Q (3 * C_ * C_ / 4)        // 786432
#define N4P (C_ * C_ / 4)            // 262144
#define N4ALL (N4X + N4Q + N4P)

__global__ void decomp_all(const float* __restrict__ x,
                           const float* __restrict__ wq,
                           const float* __restrict__ wp,
                           __half* __restrict__ xh,
                           __half* __restrict__ wqh,
                           __half* __restrict__ wph) {
    int i = blockIdx.x * blockDim.x + threadIdx.x;
    if (i < N4X) {
        float4 v = ((const float4*)x)[i];
        ((uint32_t*)xh)[i * 2 + 0] = pack_h2(v.x, v.y);
        ((uint32_t*)xh)[i * 2 + 1] = pack_h2(v.z, v.w);
    } else if (i < N4X + N4Q) {
        int j = i - N4X;
        float4 v = ((const float4*)wq)[j];
        // rows [0,C) of w_qkv produce Q -> fold softmax scale (exact pow2)
        float s = (j < C_ * C_ / 4) ? 0.125f : 1.0f;
        ((uint32_t*)wqh)[j * 2 + 0] = pack_h2(v.x * s, v.y * s);
        ((uint32_t*)wqh)[j * 2 + 1] = pack_h2(v.z * s, v.w * s);
    } else if (i < N4ALL) {
        int j = i - N4X - N4Q;
        float4 v = ((const float4*)wp)[j];
        ((uint32_t*)wph)[j * 2 + 0] = pack_h2(v.x, v.y);
        ((uint32_t*)wph)[j * 2 + 1] = pack_h2(v.z, v.w);
    }
}

// ---------------------------------------------------------------------------
// Prep: K fp16 [bh][M][D] + Vt fp16 [bh][D][M]; sources: ctx fp32 / qkv fp16
// ---------------------------------------------------------------------------
__global__ void prepkv_kernel(const __half* __restrict__ qkv, const float* __restrict__ ctx,
                              __half* __restrict__ kh, __half* __restrict__ vth) {
    __shared__ float sv[64][65];
    const int tid = threadIdx.x;
    const int kv0 = blockIdx.x * 64;
    const int bh  = blockIdx.y;
    const int b = bh >> 4, h = bh & 15;

#pragma unroll
    for (int it = 0; it < 4; it++) {
        int idx = tid + it * 256;
        int r  = idx >> 4;          // kv row 0..63
        int dc = idx & 15;          // d chunk of 4
        int kv = kv0 + r;
        float kx[4], vx[4];
        if (kv < NC_) {
            const float* base = ctx + (((size_t)(b * NC_ + kv)) * 2 + 0) * C_ + h * D_ + dc * 4;
            float4 kvec = *(const float4*)base;
            float4 vvec = *(const float4*)(base + C_);
            kx[0] = kvec.x; kx[1] = kvec.y; kx[2] = kvec.z; kx[3] = kvec.w;
            vx[0] = vvec.x; vx[1] = vvec.y; vx[2] = vvec.z; vx[3] = vvec.w;
        } else {
            const __half* base = qkv + (((size_t)(b * N_ + kv - NC_)) * 3 + 1) * C_ + h * D_ + dc * 4;
            __half2 k0 = *(const __half2*)base, k1 = *(const __half2*)(base + 2);
            __half2 w0 = *(const __half2*)(base + C_), w1 = *(const __half2*)(base + C_ + 2);
            kx[0] = __low2float(k0); kx[1] = __high2float(k0);
            kx[2] = __low2float(k1); kx[3] = __high2float(k1);
            vx[0] = __low2float(w0); vx[1] = __high2float(w0);
            vx[2] = __low2float(w1); vx[3] = __high2float(w1);
        }
        size_t o = (((size_t)bh) * M_ + kv) * D_ + dc * 4;
        *(uint32_t*)(kh + o)     = pack_h2(kx[0], kx[1]);
        *(uint32_t*)(kh + o + 2) = pack_h2(kx[2], kx[3]);
        sv[r][dc * 4 + 0] = vx[0]; sv[r][dc * 4 + 1] = vx[1];
        sv[r][dc * 4 + 2] = vx[2]; sv[r][dc * 4 + 3] = vx[3];
    }
    __syncthreads();

    {
        int d  = tid >> 2;
        int q4 = (tid & 3) * 16;
        size_t o = ((size_t)bh) * D_ * M_ + (size_t)d * M_ + kv0 + q4;
#pragma unroll
        for (int k2 = 0; k2 < 8; k2++) {
            *(uint32_t*)(vth + o + k2 * 2) =
                pack_h2(sv[q4 + k2 * 2][d], sv[q4 + k2 * 2 + 1][d]);
        }
    }
}

// ---------------------------------------------------------------------------
// mma.sync fp16 GEMM: C[M,N] = A[M,K] @ B[N,K]^T (+ bias)
// 128x128 tile, K-chunk 64, 8 warps (2x4), 3-stage cp.async, 2 CTAs/SM,
// ONE __syncthreads per K-iteration.
// ---------------------------------------------------------------------------
#define GKC 64
#define TILE_B 16384
#define STAGE_BYTES (2 * TILE_B)           // A, B
#define GEMM_SMEM (3 * STAGE_BYTES + 1024)

__device__ __forceinline__ void load_tile(const __half* __restrict__ src,
                                          int rbase, int K, int k0,
                                          uint32_t tb, int tid) {
#pragma unroll
    for (int i = 0; i < 4; i++) {
        int idx = tid + i * 256;
        int r = idx >> 3;
        int c = idx & 7;
        const void* g = src + (size_t)(rbase + r) * K + k0 + c * 8;
        cpa16(tb + sw128((uint32_t)(r * 128 + c * 16)), g);
    }
}

template <bool OUTHALF>
__global__ __launch_bounds__(256, 2) void gemm_mma(
    const __half* __restrict__ A, const __half* __restrict__ Bm,
    const float* __restrict__ bias,
    float* __restrict__ Cf, __half* __restrict__ Ch,
    int M, int N, int K)
{
    extern __shared__ char sm[];
    const uint32_t tiles = (smem_u32(sm) + 1023) & ~1023u;

    const int tid  = threadIdx.x;
    const int lane = tid & 31;
    const int wid  = tid >> 5;
    const int wm0  = (wid >> 2) * 64;
    const int wn0  = (wid & 3) * 32;
    const int bm = blockIdx.y * 128;
    const int bn = blockIdx.x * 128;

    const int lr = lane & 15;
    const int lc = (lane >> 4) << 4;

    float acc[4][4][4];
#pragma unroll
    for (int i = 0; i < 4; i++)
#pragma unroll
        for (int j = 0; j < 4; j++)
#pragma unroll
            for (int t = 0; t < 4; t++) acc[i][j][t] = 0.0f;

    const int NCH = K / GKC;   // 16

    // preload stages 0,1 as separate commit groups
    {
        load_tile(A,  bm, K, 0, tiles,          tid);
        load_tile(Bm, bn, K, 0, tiles + TILE_B, tid);
        cpa_commit();
        load_tile(A,  bm, K, GKC, tiles + STAGE_BYTES,          tid);
        load_tile(Bm, bn, K, GKC, tiles + STAGE_BYTES + TILE_B, tid);
        cpa_commit();
    }

    int stage = 0;
    for (int k = 0; k < NCH; k++) {
        if (k + 1 < NCH) cpa_wait<1>(); else cpa_wait<0>();
        __syncthreads();
        if (k + 2 < NCH) {
            int ns = (stage + 2); if (ns >= 3) ns -= 3;
            uint32_t st = tiles + ns * STAGE_BYTES;
            const int k0 = (k + 2) * GKC;
            load_tile(A,  bm, K, k0, st,          tid);
            load_tile(Bm, bn, K, k0, st + TILE_B, tid);
            cpa_commit();
        }

        const uint32_t tA = tiles + stage * STAGE_BYTES;
        const uint32_t tB = tA + TILE_B;

#pragma unroll
        for (int kk = 0; kk < 4; kk++) {
            uint32_t af[4][4], bf[2][4];
#pragma unroll
            for (int mt = 0; mt < 4; mt++) {
                uint32_t o = sw128((uint32_t)((wm0 + mt * 16 + lr) * 128 + kk * 32 + lc));
                ldsm_x4(af[mt], tA + o);
            }
#pragma unroll
            for (int ng = 0; ng < 2; ng++) {
                uint32_t o = sw128((uint32_t)((wn0 + ng * 16 + lr) * 128 + kk * 32 + lc));
                ldsm_x4(bf[ng], tB + o);
            }
#pragma unroll
            for (int mt = 0; mt < 4; mt++)
#pragma unroll
                for (int nt = 0; nt < 4; nt++) {
                    const int ng = nt >> 1, s = nt & 1;
                    mma_fp16(acc[mt][nt], af[mt], bf[ng][s], bf[ng][2 + s]);
                }
        }
        if (++stage >= 3) stage = 0;
    }

    const int gq = lane >> 2;
    const int tg = lane & 3;
#pragma unroll
    for (int mt = 0; mt < 4; mt++) {
        const int row0 = bm + wm0 + mt * 16 + gq;
#pragma unroll
        for (int nt = 0; nt < 4; nt++) {
            const int col = bn + wn0 + nt * 8 + tg * 2;
            if (OUTHALF) {
                *(uint32_t*)(Ch + (size_t)row0 * N + col) =
                    pack_h2(acc[mt][nt][0], acc[mt][nt][1]);
                *(uint32_t*)(Ch + (size_t)(row0 + 8) * N + col) =
                    pack_h2(acc[mt][nt][2], acc[mt][nt][3]);
            } else {
                float b0v = bias[col], b1v = bias[col + 1];
                float2 v0 = make_float2(acc[mt][nt][0] + b0v, acc[mt][nt][1] + b1v);
                float2 v1 = make_float2(acc[mt][nt][2] + b0v, acc[mt][nt][3] + b1v);
                *(float2*)(Cf + (size_t)row0 * N + col)       = v0;
                *(float2*)(Cf + (size_t)(row0 + 8) * N + col) = v1;
            }
        }
    }
}

// ---------------------------------------------------------------------------
// Flash attention via mma.sync, pure fp16, 3-stage cp.async, 1 sync/iter.
// CTA: 128 queries x (b,h). Q read directly from qkvh (stride 3C, pre-scaled).
// smem: Q 16KB + 3 stages x (K 8KB + Vt 8KB) = 64KB
// ---------------------------------------------------------------------------
#define AT_STAGE 16384
#define AT_SMEM (16384 + 3 * AT_STAGE + 1024)

__device__ __forceinline__ void at_load_kv(
    const __half* kh, const __half* vth, int kv0, uint32_t st, int tid)
{
#pragma unroll
    for (int i = 0; i < 2; i++) {
        int idx = tid + i * 256;
        int r = idx >> 3;        // 0..63
        int c = idx & 7;
        uint32_t so = sw128((uint32_t)(r * 128 + c * 16));
        cpa16(st + so,        kh  + (size_t)(kv0 + r) * D_ + c * 8);
        cpa16(st + 8192 + so, vth + (size_t)r * M_ + kv0 + c * 8);
    }
}

__global__ __launch_bounds__(256, 2) void attn_mma(
    const __half* __restrict__ qkv, const __half* __restrict__ Kh,
    const __half* __restrict__ Vth, __half* __restrict__ oh)
{
    extern __shared__ char sm[];
    const uint32_t base = (smem_u32(sm) + 1023) & ~1023u;
    const uint32_t sQ = base;
    const uint32_t sStage = base + 16384;

    const int tid  = threadIdx.x;
    const int lane = tid & 31;
    const int wid  = tid >> 5;
    const int qt = blockIdx.x;
    const int h  = blockIdx.y;
    const int b  = blockIdx.z;
    const int bh = b * H_ + h;

    // Q directly from fp16 qkv slot 0 (pre-scaled via weights), row stride 3C
    const __half* qg  = qkv + ((size_t)(b * N_ + qt * 128) * 3) * C_ + h * D_;
    const __half* khg = Kh + (size_t)bh * M_ * D_;
    const __half* vhg = Vth + (size_t)bh * D_ * M_;

    // group 0: Q tile (128 rows x 128B) + kv stage 0
#pragma unroll
    for (int i = 0; i < 4; i++) {
        int idx = tid + i * 256;
        int r = idx >> 3;        // 0..127
        int c = idx & 7;
        cpa16(sQ + sw128((uint32_t)(r * 128 + c * 16)),
              qg + (size_t)r * 3 * C_ + c * 8);
    }
    at_load_kv(khg, vhg, 0, sStage, tid);
    cpa_commit();
    // group 1: kv stage 1
    at_load_kv(khg, vhg, 64, sStage + AT_STAGE, tid);
    cpa_commit();

    const int lr = lane & 15;
    const int lc = (lane >> 4) << 4;
    const int w16 = wid * 16;

    uint32_t qf[4][4];
    float O[8][4];
#pragma unroll
    for (int nt = 0; nt < 8; nt++)
#pragma unroll
        for (int t = 0; t < 4; t++) O[nt][t] = 0.0f;
    float m0 = -1e30f, m1 = -1e30f, l0 = 0.0f, l1 = 0.0f;

    int stage = 0;
    for (int kt = 0; kt < KVT; kt++) {
        if (kt + 1 < KVT) cpa_wait<1>(); else cpa_wait<0>();
        __syncthreads();
        if (kt + 2 < KVT) {
            int ns = stage + 2; if (ns >= 3) ns -= 3;
            at_load_kv(khg, vhg, (kt + 2) * 64, sStage + ns * AT_STAGE, tid);
            cpa_commit();
        }

        if (kt == 0) {
#pragma unroll
            for (int kk = 0; kk < 4; kk++) {
                uint32_t o = sw128((uint32_t)((w16 + lr) * 128 + kk * 32 + lc));
                ldsm_x4(qf[kk], sQ + o);
            }
        }

        const uint32_t tK = sStage + stage * AT_STAGE;
        const uint32_t tV = tK + 8192;

        // ---- S = Q . K^T ----
        float S[8][4];
#pragma unroll
        for (int nt = 0; nt < 8; nt++)
#pragma unroll
            for (int t = 0; t < 4; t++) S[nt][t] = 0.0f;

#pragma unroll
        for (int kk = 0; kk < 4; kk++) {
            uint32_t bf[4][4];
#pragma unroll
            for (int ng = 0; ng < 4; ng++) {
                uint32_t o = sw128((uint32_t)((ng * 16 + lr) * 128 + kk * 32 + lc));
                ldsm_x4(bf[ng], tK + o);
            }
#pragma unroll
            for (int ng = 0; ng < 4; ng++)
#pragma unroll
                for (int s = 0; s < 2; s++)
                    mma_fp16(S[ng * 2 + s], qf[kk], bf[ng][s], bf[ng][2 + s]);
        }

        // ---- online softmax ----
        float mt0 = -1e30f, mt1 = -1e30f;
#pragma unroll
        for (int nt = 0; nt < 8; nt++) {
            mt0 = fmaxf(mt0, fmaxf(S[nt][0], S[nt][1]));
            mt1 = fmaxf(mt1, fmaxf(S[nt][2], S[nt][3]));
        }
        mt0 = fmaxf(mt0, __shfl_xor_sync(0xffffffffu, mt0, 1));
        mt0 = fmaxf(mt0, __shfl_xor_sync(0xffffffffu, mt0, 2));
        mt1 = fmaxf(mt1, __shfl_xor_sync(0xffffffffu, mt1, 1));
        mt1 = fmaxf(mt1, __shfl_xor_sync(0xffffffffu, mt1, 2));

        float mn0 = fmaxf(m0, mt0), mn1 = fmaxf(m1, mt1);
        float a0 = __expf(m0 - mn0), a1 = __expf(m1 - mn1);
        m0 = mn0; m1 = mn1;

        float rs0 = 0.0f, rs1 = 0.0f;
#pragma unroll
        for (int nt = 0; nt < 8; nt++) {
            S[nt][0] = __expf(S[nt][0] - m0);
            S[nt][1] = __expf(S[nt][1] - m0);
            S[nt][2] = __expf(S[nt][2] - m1);
            S[nt][3] = __expf(S[nt][3] - m1);
            rs0 += S[nt][0] + S[nt][1];
            rs1 += S[nt][2] + S[nt][3];
        }
        rs0 += __shfl_xor_sync(0xffffffffu, rs0, 1);
        rs0 += __shfl_xor_sync(0xffffffffu, rs0, 2);
        rs1 += __shfl_xor_sync(0xffffffffu, rs1, 1);
        rs1 += __shfl_xor_sync(0xffffffffu, rs1, 2);
        l0 = l0 * a0 + rs0;
        l1 = l1 * a1 + rs1;

#pragma unroll
        for (int nt = 0; nt < 8; nt++) {
            O[nt][0] *= a0; O[nt][1] *= a0;
            O[nt][2] *= a1; O[nt][3] *= a1;
        }

        // ---- pack P fp16 A-fragments ----
        uint32_t ph[4][4];
#pragma unroll
        for (int j = 0; j < 4; j++) {
            ph[j][0] = pack_h2(S[2 * j][0],     S[2 * j][1]);
            ph[j][1] = pack_h2(S[2 * j][2],     S[2 * j][3]);
            ph[j][2] = pack_h2(S[2 * j + 1][0], S[2 * j + 1][1]);
            ph[j][3] = pack_h2(S[2 * j + 1][2], S[2 * j + 1][3]);
        }

        // ---- O += P . Vt^T ----
#pragma unroll
        for (int j = 0; j < 4; j++) {
            uint32_t vf[4][4];
#pragma unroll
            for (int ng = 0; ng < 4; ng++) {
                uint32_t o = sw128((uint32_t)((ng * 16 + lr) * 128 + j * 32 + lc));
                ldsm_x4(vf[ng], tV + o);
            }
#pragma unroll
            for (int ng = 0; ng < 4; ng++)
#pragma unroll
                for (int s = 0; s < 2; s++)
                    mma_fp16(O[ng * 2 + s], ph[j], vf[ng][s], vf[ng][2 + s]);
        }
        if (++stage >= 3) stage = 0;
    }

    // ---- epilogue: O/l -> fp16 at (b, n, h*64 + d) ----
    const float inv0 = 1.0f / l0, inv1 = 1.0f / l1;
    const int g  = lane >> 2;
    const int tg = lane & 3;
    const int n0 = qt * 128 + w16 + g;
#pragma unroll
    for (int nt = 0; nt < 8; nt++) {
        const int col = h * D_ + nt * 8 + tg * 2;
        *(uint32_t*)(oh + (size_t)(b * N_ + n0) * C_ + col) =
            pack_h2(O[nt][0] * inv0, O[nt][1] * inv0);
        *(uint32_t*)(oh + (size_t)(b * N_ + n0 + 8) * C_ + col) =
            pack_h2(O[nt][2] * inv1, O[nt][3] * inv1);
    }
}

// ---------------------------------------------------------------------------
extern "C" void kernel_launch(void* const* d_in, const int* in_sizes, int n_in,
                              void* d_out, int out_size) {
    const float* x      = (const float*)d_in[0];
    const float* ctx    = (const float*)d_in[1];
    const float* w_qkv  = (const float*)d_in[2];
    const float* w_proj = (const float*)d_in[3];
    const float* b_proj = (const float*)d_in[4];
    float* out = (float*)d_out;

    void *p;
    cudaGetSymbolAddress(&p, g_qkvh);  __half* qkvh = (__half*)p;
    cudaGetSymbolAddress(&p, g_xh);    __half* xh   = (__half*)p;
    cudaGetSymbolAddress(&p, g_wqkv);  __half* wq   = (__half*)p;
    cudaGetSymbolAddress(&p, g_wproj); __half* wp   = (__half*)p;
    cudaGetSymbolAddress(&p, g_ah);    __half* ah   = (__half*)p;
    cudaGetSymbolAddress(&p, g_kh);    __half* kh   = (__half*)p;
    cudaGetSymbolAddress(&p, g_vth);   __half* vth  = (__half*)p;

    cudaFuncSetAttribute(gemm_mma<true>,  cudaFuncAttributeMaxDynamicSharedMemorySize, GEMM_SMEM);
    cudaFuncSetAttribute(gemm_mma<false>, cudaFuncAttributeMaxDynamicSharedMemorySize, GEMM_SMEM);
    cudaFuncSetAttribute(attn_mma,        cudaFuncAttributeMaxDynamicSharedMemorySize, AT_SMEM);

    // 0) convert inputs/weights to fp16 (single launch; Q-rows of w_qkv scaled)
    decomp_all<<<(N4ALL + 255) / 256, 256>>>(x, w_qkv, w_proj, xh, wq, wp);

    // 1) QKV projection -> fp16 qkv (Q pre-scaled)
    {
        dim3 grid(3 * C_ / 128, B_ * N_ / 128);
        gemm_mma<true><<<grid, 256, GEMM_SMEM>>>(xh, wq, nullptr, nullptr, qkvh,
                                                 B_ * N_, 3 * C_, C_);
    }

    // 1.5) K gather + V transpose
    {
        dim3 grid(KVT, B_ * H_);
        prepkv_kernel<<<grid, 256>>>(qkvh, ctx, kh, vth);
    }

    // 2) Attention
    {
        dim3 grid(N_ / 128, H_, B_);
        attn_mma<<<grid, 256, AT_SMEM>>>(qkvh, kh, vth, ah);
    }

    // 3) Output projection with bias -> fp32 out
    {
        dim3 grid(C_ / 128, B_ * N_ / 128);
        gemm_mma<false><<<grid, 256, GEMM_SMEM>>>(ah, wp, b_proj, out, nullptr,
                                                  B_ * N_, C_, C_);
    }
}

// round 9
// speedup vs baseline: 8.4158x; 1.0517x over previous
#include <cuda_runtime.h>
#include <cuda_fp16.h>
#include <cstdint>
#include <math.h>

// Problem constants (fixed by setup_inputs)
#define B_   4
#define N_   1024
#define C_   1024
#define H_   16
#define D_   64
#define NC_  256
#define M_   1280            // NC_ + N_
#define KVT  20              // M_/64 kv tiles

// ---------------------------------------------------------------------------
// Scratch (allocation-free rule: __device__ globals)
// ---------------------------------------------------------------------------
__device__ __half g_qkvh[(size_t)B_ * N_ * 3 * C_];           // GEMM1 out (Q pre-scaled, log2-domain)
__device__ __half g_xh[(size_t)B_ * N_ * C_];                 // x fp16
__device__ __half g_wqkv[(size_t)3 * C_ * C_];                // Q-rows scaled by 0.125*log2e
__device__ __half g_wproj[(size_t)C_ * C_];
__device__ __half g_ah[(size_t)B_ * N_ * C_];                 // attn out fp16
__device__ __half g_kh[(size_t)B_ * H_ * M_ * D_];
__device__ __half g_vth[(size_t)B_ * H_ * D_ * M_];           // V^T [d][kv]

// ---------------------------------------------------------------------------
// Helpers (sm_100 baseline PTX only)
// ---------------------------------------------------------------------------
__device__ __forceinline__ uint32_t smem_u32(const void* p) {
    uint32_t a;
    asm("{ .reg .u64 t; cvta.to.shared.u64 t, %1; cvt.u32.u64 %0, t; }" : "=r"(a) : "l"(p));
    return a;
}
__device__ __forceinline__ void cpa16(uint32_t d, const void* g) {
    asm volatile("cp.async.cg.shared.global [%0], [%1], 16;" :: "r"(d), "l"(g));
}
__device__ __forceinline__ void cpa_commit() { asm volatile("cp.async.commit_group;"); }
template <int n> __device__ __forceinline__ void cpa_wait() {
    asm volatile("cp.async.wait_group %0;" :: "n"(n));
}
__device__ __forceinline__ uint32_t sw128(uint32_t off) { return off ^ ((off >> 3) & 0x70); }

__device__ __forceinline__ void ldsm_x4(uint32_t* r, uint32_t addr) {
    asm volatile("ldmatrix.sync.aligned.m8n8.x4.shared.b16 {%0,%1,%2,%3}, [%4];"
        : "=r"(r[0]), "=r"(r[1]), "=r"(r[2]), "=r"(r[3]) : "r"(addr));
}
__device__ __forceinline__ void mma_fp16(float* d, const uint32_t* a,
                                         uint32_t b0, uint32_t b1) {
    asm volatile(
        "mma.sync.aligned.m16n8k16.row.col.f32.f16.f16.f32 "
        "{%0,%1,%2,%3},{%4,%5,%6,%7},{%8,%9},{%0,%1,%2,%3};"
        : "+f"(d[0]), "+f"(d[1]), "+f"(d[2]), "+f"(d[3])
        : "r"(a[0]), "r"(a[1]), "r"(a[2]), "r"(a[3]), "r"(b0), "r"(b1));
}
__device__ __forceinline__ uint32_t pack_h2(float a, float b) {
    __half2 t = __floats2half2_rn(a, b);
    return *(uint32_t*)&t;
}
__device__ __forceinline__ float fexp2(float x) {
    float y;
    asm("ex2.approx.ftz.f32 %0, %1;" : "=f"(y) : "f"(x));
    return y;
}

// ---------------------------------------------------------------------------
// One-shot fp32 -> fp16 conversion of x, w_qkv (Q rows scaled), w_proj
// ---------------------------------------------------------------------------
#define N4X (B_ * N_ * C_ / 4)       // 1048576
#define N4Q (3 * C_ * C_ / 4)        // 786432
#define N4P (C_ * C_ / 4)            // 262144
#define N4ALL (N4X + N4Q + N4P)
#define QSCALE (0.125f * 1.4426950408889634f)   // fold softmax scale + log2e

__global__ void decomp_all(const float* __restrict__ x,
                           const float* __restrict__ wq,
                           const float* __restrict__ wp,
                           __half* __restrict__ xh,
                           __half* __restrict__ wqh,
                           __half* __restrict__ wph) {
    int i = blockIdx.x * blockDim.x + threadIdx.x;
    if (i < N4X) {
        float4 v = ((const float4*)x)[i];
        ((uint32_t*)xh)[i * 2 + 0] = pack_h2(v.x, v.y);
        ((uint32_t*)xh)[i * 2 + 1] = pack_h2(v.z, v.w);
    } else if (i < N4X + N4Q) {
        int j = i - N4X;
        float4 v = ((const float4*)wq)[j];
        // rows [0,C) of w_qkv produce Q -> fold softmax scale * log2e
        float s = (j < C_ * C_ / 4) ? QSCALE : 1.0f;
        ((uint32_t*)wqh)[j * 2 + 0] = pack_h2(v.x * s, v.y * s);
        ((uint32_t*)wqh)[j * 2 + 1] = pack_h2(v.z * s, v.w * s);
    } else if (i < N4ALL) {
        int j = i - N4X - N4Q;
        float4 v = ((const float4*)wp)[j];
        ((uint32_t*)wph)[j * 2 + 0] = pack_h2(v.x, v.y);
        ((uint32_t*)wph)[j * 2 + 1] = pack_h2(v.z, v.w);
    }
}

// ---------------------------------------------------------------------------
// Prep: K fp16 [bh][M][D] + Vt fp16 [bh][D][M]; sources: ctx fp32 / qkv fp16
// ---------------------------------------------------------------------------
__global__ void prepkv_kernel(const __half* __restrict__ qkv, const float* __restrict__ ctx,
                              __half* __restrict__ kh, __half* __restrict__ vth) {
    __shared__ float sv[64][65];
    const int tid = threadIdx.x;
    const int kv0 = blockIdx.x * 64;
    const int bh  = blockIdx.y;
    const int b = bh >> 4, h = bh & 15;

#pragma unroll
    for (int it = 0; it < 4; it++) {
        int idx = tid + it * 256;
        int r  = idx >> 4;          // kv row 0..63
        int dc = idx & 15;          // d chunk of 4
        int kv = kv0 + r;
        float kx[4], vx[4];
        if (kv < NC_) {
            const float* base = ctx + (((size_t)(b * NC_ + kv)) * 2 + 0) * C_ + h * D_ + dc * 4;
            float4 kvec = *(const float4*)base;
            float4 vvec = *(const float4*)(base + C_);
            kx[0] = kvec.x; kx[1] = kvec.y; kx[2] = kvec.z; kx[3] = kvec.w;
            vx[0] = vvec.x; vx[1] = vvec.y; vx[2] = vvec.z; vx[3] = vvec.w;
        } else {
            const __half* base = qkv + (((size_t)(b * N_ + kv - NC_)) * 3 + 1) * C_ + h * D_ + dc * 4;
            __half2 k0 = *(const __half2*)base, k1 = *(const __half2*)(base + 2);
            __half2 w0 = *(const __half2*)(base + C_), w1 = *(const __half2*)(base + C_ + 2);
            kx[0] = __low2float(k0); kx[1] = __high2float(k0);
            kx[2] = __low2float(k1); kx[3] = __high2float(k1);
            vx[0] = __low2float(w0); vx[1] = __high2float(w0);
            vx[2] = __low2float(w1); vx[3] = __high2float(w1);
        }
        size_t o = (((size_t)bh) * M_ + kv) * D_ + dc * 4;
        *(uint32_t*)(kh + o)     = pack_h2(kx[0], kx[1]);
        *(uint32_t*)(kh + o + 2) = pack_h2(kx[2], kx[3]);
        sv[r][dc * 4 + 0] = vx[0]; sv[r][dc * 4 + 1] = vx[1];
        sv[r][dc * 4 + 2] = vx[2]; sv[r][dc * 4 + 3] = vx[3];
    }
    __syncthreads();

    {
        int d  = tid >> 2;
        int q4 = (tid & 3) * 16;
        size_t o = ((size_t)bh) * D_ * M_ + (size_t)d * M_ + kv0 + q4;
#pragma unroll
        for (int k2 = 0; k2 < 8; k2++) {
            *(uint32_t*)(vth + o + k2 * 2) =
                pack_h2(sv[q4 + k2 * 2][d], sv[q4 + k2 * 2 + 1][d]);
        }
    }
}

// ---------------------------------------------------------------------------
// mma.sync fp16 GEMM: C[M,N] = A[M,K] @ B[N,K]^T (+ bias)
// 128x128 tile, K-chunk 64, 8 warps (2x4), 3-stage cp.async, 2 CTAs/SM,
// separable swizzle addressing, ONE __syncthreads per K-iteration.
// ---------------------------------------------------------------------------
#define GKC 64
#define TILE_B 16384
#define STAGE_BYTES (2 * TILE_B)           // A, B
#define GEMM_SMEM (3 * STAGE_BYTES + 1024)

__device__ __forceinline__ void load_tile(const __half* __restrict__ src,
                                          int rbase, int K, int k0,
                                          uint32_t tb, int tid) {
#pragma unroll
    for (int i = 0; i < 4; i++) {
        int idx = tid + i * 256;
        int r = idx >> 3;
        int c = idx & 7;
        const void* g = src + (size_t)(rbase + r) * K + k0 + c * 8;
        cpa16(tb + sw128((uint32_t)(r * 128 + c * 16)), g);
    }
}

template <bool OUTHALF>
__global__ __launch_bounds__(256, 2) void gemm_mma(
    const __half* __restrict__ A, const __half* __restrict__ Bm,
    const float* __restrict__ bias,
    float* __restrict__ Cf, __half* __restrict__ Ch,
    int M, int N, int K)
{
    extern __shared__ char sm[];
    const uint32_t tiles = (smem_u32(sm) + 1023) & ~1023u;

    const int tid  = threadIdx.x;
    const int lane = tid & 31;
    const int wid  = tid >> 5;
    const int wm0  = (wid >> 2) * 64;
    const int wn0  = (wid & 3) * 32;
    const int bm = blockIdx.y * 128;
    const int bn = blockIdx.x * 128;

    const int lr = lane & 15;
    const int lc = (lane >> 4) << 4;
    const uint32_t xv = (uint32_t)((lr & 7) << 4);   // per-thread swizzle XOR

    // separable swizzled offsets: addr = stage_base + rowoff + colx
    uint32_t arow[4], brow[2], colx[4];
#pragma unroll
    for (int mt = 0; mt < 4; mt++) arow[mt] = (uint32_t)((wm0 + mt * 16 + lr) * 128);
#pragma unroll
    for (int ng = 0; ng < 2; ng++) brow[ng] = (uint32_t)((wn0 + ng * 16 + lr) * 128) + TILE_B;
#pragma unroll
    for (int kk = 0; kk < 4; kk++) colx[kk] = ((uint32_t)(kk * 32 + lc)) ^ xv;

    float acc[4][4][4];
#pragma unroll
    for (int i = 0; i < 4; i++)
#pragma unroll
        for (int j = 0; j < 4; j++)
#pragma unroll
            for (int t = 0; t < 4; t++) acc[i][j][t] = 0.0f;

    const int NCH = K / GKC;   // 16

    {
        load_tile(A,  bm, K, 0, tiles,          tid);
        load_tile(Bm, bn, K, 0, tiles + TILE_B, tid);
        cpa_commit();
        load_tile(A,  bm, K, GKC, tiles + STAGE_BYTES,          tid);
        load_tile(Bm, bn, K, GKC, tiles + STAGE_BYTES + TILE_B, tid);
        cpa_commit();
    }

    int stage = 0;
    for (int k = 0; k < NCH; k++) {
        if (k + 1 < NCH) cpa_wait<1>(); else cpa_wait<0>();
        __syncthreads();
        if (k + 2 < NCH) {
            int ns = (stage + 2); if (ns >= 3) ns -= 3;
            uint32_t st = tiles + ns * STAGE_BYTES;
            const int k0 = (k + 2) * GKC;
            load_tile(A,  bm, K, k0, st,          tid);
            load_tile(Bm, bn, K, k0, st + TILE_B, tid);
            cpa_commit();
        }

        const uint32_t sb = tiles + stage * STAGE_BYTES;

#pragma unroll
        for (int kk = 0; kk < 4; kk++) {
            uint32_t af[4][4], bf[2][4];
#pragma unroll
            for (int mt = 0; mt < 4; mt++)
                ldsm_x4(af[mt], sb + arow[mt] + colx[kk]);
#pragma unroll
            for (int ng = 0; ng < 2; ng++)
                ldsm_x4(bf[ng], sb + brow[ng] + colx[kk]);
#pragma unroll
            for (int mt = 0; mt < 4; mt++)
#pragma unroll
                for (int nt = 0; nt < 4; nt++) {
                    const int ng = nt >> 1, s = nt & 1;
                    mma_fp16(acc[mt][nt], af[mt], bf[ng][s], bf[ng][2 + s]);
                }
        }
        if (++stage >= 3) stage = 0;
    }

    const int gq = lane >> 2;
    const int tg = lane & 3;
#pragma unroll
    for (int mt = 0; mt < 4; mt++) {
        const int row0 = bm + wm0 + mt * 16 + gq;
#pragma unroll
        for (int nt = 0; nt < 4; nt++) {
            const int col = bn + wn0 + nt * 8 + tg * 2;
            if (OUTHALF) {
                *(uint32_t*)(Ch + (size_t)row0 * N + col) =
                    pack_h2(acc[mt][nt][0], acc[mt][nt][1]);
                *(uint32_t*)(Ch + (size_t)(row0 + 8) * N + col) =
                    pack_h2(acc[mt][nt][2], acc[mt][nt][3]);
            } else {
                float b0v = bias[col], b1v = bias[col + 1];
                float2 v0 = make_float2(acc[mt][nt][0] + b0v, acc[mt][nt][1] + b1v);
                float2 v1 = make_float2(acc[mt][nt][2] + b0v, acc[mt][nt][3] + b1v);
                *(float2*)(Cf + (size_t)row0 * N + col)       = v0;
                *(float2*)(Cf + (size_t)(row0 + 8) * N + col) = v1;
            }
        }
    }
}

// ---------------------------------------------------------------------------
// Flash attention via mma.sync, pure fp16, 3-stage cp.async, base-2 softmax,
// separable swizzle addressing. CTA: 128 queries x (b,h).
// smem: Q 16KB + 3 stages x (K 8KB + Vt 8KB) = 64KB
// ---------------------------------------------------------------------------
#define AT_STAGE 16384
#define AT_SMEM (16384 + 3 * AT_STAGE + 1024)

__device__ __forceinline__ void at_load_kv(
    const __half* kh, const __half* vth, int kv0, uint32_t st, int tid)
{
#pragma unroll
    for (int i = 0; i < 2; i++) {
        int idx = tid + i * 256;
        int r = idx >> 3;        // 0..63
        int c = idx & 7;
        uint32_t so = sw128((uint32_t)(r * 128 + c * 16));
        cpa16(st + so,        kh  + (size_t)(kv0 + r) * D_ + c * 8);
        cpa16(st + 8192 + so, vth + (size_t)r * M_ + kv0 + c * 8);
    }
}

__global__ __launch_bounds__(256, 2) void attn_mma(
    const __half* __restrict__ qkv, const __half* __restrict__ Kh,
    const __half* __restrict__ Vth, __half* __restrict__ oh)
{
    extern __shared__ char sm[];
    const uint32_t base = (smem_u32(sm) + 1023) & ~1023u;
    const uint32_t sQ = base;
    const uint32_t sStage = base + 16384;

    const int tid  = threadIdx.x;
    const int lane = tid & 31;
    const int wid  = tid >> 5;
    const int qt = blockIdx.x;
    const int h  = blockIdx.y;
    const int b  = blockIdx.z;
    const int bh = b * H_ + h;

    const __half* qg  = qkv + ((size_t)(b * N_ + qt * 128) * 3) * C_ + h * D_;
    const __half* khg = Kh + (size_t)bh * M_ * D_;
    const __half* vhg = Vth + (size_t)bh * D_ * M_;

#pragma unroll
    for (int i = 0; i < 4; i++) {
        int idx = tid + i * 256;
        int r = idx >> 3;        // 0..127
        int c = idx & 7;
        cpa16(sQ + sw128((uint32_t)(r * 128 + c * 16)),
              qg + (size_t)r * 3 * C_ + c * 8);
    }
    at_load_kv(khg, vhg, 0, sStage, tid);
    cpa_commit();
    at_load_kv(khg, vhg, 64, sStage + AT_STAGE, tid);
    cpa_commit();

    const int lr = lane & 15;
    const int lc = (lane >> 4) << 4;
    const int w16 = wid * 16;
    const uint32_t xv = (uint32_t)((lr & 7) << 4);

    // separable swizzled offsets
    uint32_t rowo[4], colx[4];
#pragma unroll
    for (int ng = 0; ng < 4; ng++) rowo[ng] = (uint32_t)((ng * 16 + lr) * 128);
#pragma unroll
    for (int kk = 0; kk < 4; kk++) colx[kk] = ((uint32_t)(kk * 32 + lc)) ^ xv;

    uint32_t qf[4][4];
    float O[8][4];
#pragma unroll
    for (int nt = 0; nt < 8; nt++)
#pragma unroll
        for (int t = 0; t < 4; t++) O[nt][t] = 0.0f;
    float m0 = -1e30f, m1 = -1e30f, l0 = 0.0f, l1 = 0.0f;

    int stage = 0;
    for (int kt = 0; kt < KVT; kt++) {
        if (kt + 1 < KVT) cpa_wait<1>(); else cpa_wait<0>();
        __syncthreads();
        if (kt + 2 < KVT) {
            int ns = stage + 2; if (ns >= 3) ns -= 3;
            at_load_kv(khg, vhg, (kt + 2) * 64, sStage + ns * AT_STAGE, tid);
            cpa_commit();
        }

        if (kt == 0) {
            const uint32_t qrow = sQ + (uint32_t)((w16 + lr) * 128);
#pragma unroll
            for (int kk = 0; kk < 4; kk++)
                ldsm_x4(qf[kk], qrow + colx[kk]);
        }

        const uint32_t tK = sStage + stage * AT_STAGE;
        const uint32_t tV = tK + 8192;

        // ---- S = Q . K^T (log2 domain) ----
        float S[8][4];
#pragma unroll
        for (int nt = 0; nt < 8; nt++)
#pragma unroll
            for (int t = 0; t < 4; t++) S[nt][t] = 0.0f;

#pragma unroll
        for (int kk = 0; kk < 4; kk++) {
            uint32_t bf[4][4];
#pragma unroll
            for (int ng = 0; ng < 4; ng++)
                ldsm_x4(bf[ng], tK + rowo[ng] + colx[kk]);
#pragma unroll
            for (int ng = 0; ng < 4; ng++)
#pragma unroll
                for (int s = 0; s < 2; s++)
                    mma_fp16(S[ng * 2 + s], qf[kk], bf[ng][s], bf[ng][2 + s]);
        }

        // ---- online softmax (base 2) ----
        float mt0 = -1e30f, mt1 = -1e30f;
#pragma unroll
        for (int nt = 0; nt < 8; nt++) {
            mt0 = fmaxf(mt0, fmaxf(S[nt][0], S[nt][1]));
            mt1 = fmaxf(mt1, fmaxf(S[nt][2], S[nt][3]));
        }
        mt0 = fmaxf(mt0, __shfl_xor_sync(0xffffffffu, mt0, 1));
        mt0 = fmaxf(mt0, __shfl_xor_sync(0xffffffffu, mt0, 2));
        mt1 = fmaxf(mt1, __shfl_xor_sync(0xffffffffu, mt1, 1));
        mt1 = fmaxf(mt1, __shfl_xor_sync(0xffffffffu, mt1, 2));

        float mn0 = fmaxf(m0, mt0), mn1 = fmaxf(m1, mt1);
        float a0 = fexp2(m0 - mn0), a1 = fexp2(m1 - mn1);
        m0 = mn0; m1 = mn1;

        float rs0 = 0.0f, rs1 = 0.0f;
#pragma unroll
        for (int nt = 0; nt < 8; nt++) {
            S[nt][0] = fexp2(S[nt][0] - m0);
            S[nt][1] = fexp2(S[nt][1] - m0);
            S[nt][2] = fexp2(S[nt][2] - m1);
            S[nt][3] = fexp2(S[nt][3] - m1);
            rs0 += S[nt][0] + S[nt][1];
            rs1 += S[nt][2] + S[nt][3];
        }
        rs0 += __shfl_xor_sync(0xffffffffu, rs0, 1);
        rs0 += __shfl_xor_sync(0xffffffffu, rs0, 2);
        rs1 += __shfl_xor_sync(0xffffffffu, rs1, 1);
        rs1 += __shfl_xor_sync(0xffffffffu, rs1, 2);
        l0 = l0 * a0 + rs0;
        l1 = l1 * a1 + rs1;

#pragma unroll
        for (int nt = 0; nt < 8; nt++) {
            O[nt][0] *= a0; O[nt][1] *= a0;
            O[nt][2] *= a1; O[nt][3] *= a1;
        }

        // ---- pack P fp16 A-fragments ----
        uint32_t ph[4][4];
#pragma unroll
        for (int j = 0; j < 4; j++) {
            ph[j][0] = pack_h2(S[2 * j][0],     S[2 * j][1]);
            ph[j][1] = pack_h2(S[2 * j][2],     S[2 * j][3]);
            ph[j][2] = pack_h2(S[2 * j + 1][0], S[2 * j + 1][1]);
            ph[j][3] = pack_h2(S[2 * j + 1][2], S[2 * j + 1][3]);
        }

        // ---- O += P . Vt^T ----
#pragma unroll
        for (int j = 0; j < 4; j++) {
            uint32_t vf[4][4];
#pragma unroll
            for (int ng = 0; ng < 4; ng++)
                ldsm_x4(vf[ng], tV + rowo[ng] + colx[j]);
#pragma unroll
            for (int ng = 0; ng < 4; ng++)
#pragma unroll
                for (int s = 0; s < 2; s++)
                    mma_fp16(O[ng * 2 + s], ph[j], vf[ng][s], vf[ng][2 + s]);
        }
        if (++stage >= 3) stage = 0;
    }

    // ---- epilogue ----
    const float inv0 = 1.0f / l0, inv1 = 1.0f / l1;
    const int g  = lane >> 2;
    const int tg = lane & 3;
    const int n0 = qt * 128 + w16 + g;
#pragma unroll
    for (int nt = 0; nt < 8; nt++) {
        const int col = h * D_ + nt * 8 + tg * 2;
        *(uint32_t*)(oh + (size_t)(b * N_ + n0) * C_ + col) =
            pack_h2(O[nt][0] * inv0, O[nt][1] * inv0);
        *(uint32_t*)(oh + (size_t)(b * N_ + n0 + 8) * C_ + col) =
            pack_h2(O[nt][2] * inv1, O[nt][3] * inv1);
    }
}

// ---------------------------------------------------------------------------
extern "C" void kernel_launch(void* const* d_in, const int* in_sizes, int n_in,
                              void* d_out, int out_size) {
    const float* x      = (const float*)d_in[0];
    const float* ctx    = (const float*)d_in[1];
    const float* w_qkv  = (const float*)d_in[2];
    const float* w_proj = (const float*)d_in[3];
    const float* b_proj = (const float*)d_in[4];
    float* out = (float*)d_out;

    void *p;
    cudaGetSymbolAddress(&p, g_qkvh);  __half* qkvh = (__half*)p;
    cudaGetSymbolAddress(&p, g_xh);    __half* xh   = (__half*)p;
    cudaGetSymbolAddress(&p, g_wqkv);  __half* wq   = (__half*)p;
    cudaGetSymbolAddress(&p, g_wproj); __half* wp   = (__half*)p;
    cudaGetSymbolAddress(&p, g_ah);    __half* ah   = (__half*)p;
    cudaGetSymbolAddress(&p, g_kh);    __half* kh   = (__half*)p;
    cudaGetSymbolAddress(&p, g_vth);   __half* vth  = (__half*)p;

    cudaFuncSetAttribute(gemm_mma<true>,  cudaFuncAttributeMaxDynamicSharedMemorySize, GEMM_SMEM);
    cudaFuncSetAttribute(gemm_mma<false>, cudaFuncAttributeMaxDynamicSharedMemorySize, GEMM_SMEM);
    cudaFuncSetAttribute(attn_mma,        cudaFuncAttributeMaxDynamicSharedMemorySize, AT_SMEM);

    // 0) convert inputs/weights to fp16 (Q-rows of w_qkv carry 0.125*log2e)
    decomp_all<<<(N4ALL + 255) / 256, 256>>>(x, w_qkv, w_proj, xh, wq, wp);

    // 1) QKV projection -> fp16 qkv
    {
        dim3 grid(3 * C_ / 128, B_ * N_ / 128);
        gemm_mma<true><<<grid, 256, GEMM_SMEM>>>(xh, wq, nullptr, nullptr, qkvh,
                                                 B_ * N_, 3 * C_, C_);
    }

    // 1.5) K gather + V transpose
    {
        dim3 grid(KVT, B_ * H_);
        prepkv_kernel<<<grid, 256>>>(qkvh, ctx, kh, vth);
    }

    // 2) Attention (base-2 softmax)
    {
        dim3 grid(N_ / 128, H_, B_);
        attn_mma<<<grid, 256, AT_SMEM>>>(qkvh, kh, vth, ah);
    }

    // 3) Output projection with bias -> fp32 out
    {
        dim3 grid(C_ / 128, B_ * N_ / 128);
        gemm_mma<false><<<grid, 256, GEMM_SMEM>>>(ah, wp, b_proj, out, nullptr,
                                                  B_ * N_, C_, C_);
    }
}

// round 10
// speedup vs baseline: 8.6404x; 1.0267x over previous
#include <cuda_runtime.h>
#include <cuda_fp16.h>
#include <cstdint>
#include <math.h>

// Problem constants (fixed by setup_inputs)
#define B_   4
#define N_   1024
#define C_   1024
#define H_   16
#define D_   64
#define NC_  256
#define M_   1280            // NC_ + N_
#define KVT  20              // M_/64 kv tiles

// ---------------------------------------------------------------------------
// Scratch (allocation-free rule: __device__ globals)
// ---------------------------------------------------------------------------
__device__ __half g_qkvh[(size_t)B_ * N_ * 3 * C_];           // GEMM1 out (Q pre-scaled, log2-domain)
__device__ __half g_xh[(size_t)B_ * N_ * C_];                 // x fp16
__device__ __half g_wqkv[(size_t)3 * C_ * C_];                // Q-rows scaled by 0.125*log2e
__device__ __half g_wproj[(size_t)C_ * C_];
__device__ __half g_ah[(size_t)B_ * N_ * C_];                 // attn out fp16
__device__ __half g_kh[(size_t)B_ * H_ * M_ * D_];
__device__ __half g_vth[(size_t)B_ * H_ * D_ * M_];           // V^T [d][kv]

// ---------------------------------------------------------------------------
// Helpers (sm_100 baseline PTX only)
// ---------------------------------------------------------------------------
__device__ __forceinline__ uint32_t smem_u32(const void* p) {
    uint32_t a;
    asm("{ .reg .u64 t; cvta.to.shared.u64 t, %1; cvt.u32.u64 %0, t; }" : "=r"(a) : "l"(p));
    return a;
}
__device__ __forceinline__ void cpa16(uint32_t d, const void* g) {
    asm volatile("cp.async.cg.shared.global [%0], [%1], 16;" :: "r"(d), "l"(g));
}
__device__ __forceinline__ void cpa_commit() { asm volatile("cp.async.commit_group;"); }
template <int n> __device__ __forceinline__ void cpa_wait() {
    asm volatile("cp.async.wait_group %0;" :: "n"(n));
}
__device__ __forceinline__ uint32_t sw128(uint32_t off) { return off ^ ((off >> 3) & 0x70); }

__device__ __forceinline__ void ldsm_x4(uint32_t* r, uint32_t addr) {
    asm volatile("ldmatrix.sync.aligned.m8n8.x4.shared.b16 {%0,%1,%2,%3}, [%4];"
        : "=r"(r[0]), "=r"(r[1]), "=r"(r[2]), "=r"(r[3]) : "r"(addr));
}
__device__ __forceinline__ void mma_fp16(float* d, const uint32_t* a,
                                         uint32_t b0, uint32_t b1) {
    asm volatile(
        "mma.sync.aligned.m16n8k16.row.col.f32.f16.f16.f32 "
        "{%0,%1,%2,%3},{%4,%5,%6,%7},{%8,%9},{%0,%1,%2,%3};"
        : "+f"(d[0]), "+f"(d[1]), "+f"(d[2]), "+f"(d[3])
        : "r"(a[0]), "r"(a[1]), "r"(a[2]), "r"(a[3]), "r"(b0), "r"(b1));
}
__device__ __forceinline__ uint32_t pack_h2(float a, float b) {
    __half2 t = __floats2half2_rn(a, b);
    return *(uint32_t*)&t;
}
__device__ __forceinline__ float fexp2(float x) {
    float y;
    asm("ex2.approx.ftz.f32 %0, %1;" : "=f"(y) : "f"(x));
    return y;
}

// ---------------------------------------------------------------------------
// One-shot fp32 -> fp16 conversion of x, w_qkv (Q rows scaled), w_proj
// ---------------------------------------------------------------------------
#define N4X (B_ * N_ * C_ / 4)       // 1048576
#define N4Q (3 * C_ * C_ / 4)        // 786432
#define N4P (C_ * C_ / 4)            // 262144
#define N4ALL (N4X + N4Q + N4P)
#define QSCALE (0.125f * 1.4426950408889634f)   // softmax scale * log2e

__global__ void decomp_all(const float* __restrict__ x,
                           const float* __restrict__ wq,
                           const float* __restrict__ wp,
                           __half* __restrict__ xh,
                           __half* __restrict__ wqh,
                           __half* __restrict__ wph) {
    int i = blockIdx.x * blockDim.x + threadIdx.x;
    if (i < N4X) {
        float4 v = ((const float4*)x)[i];
        ((uint32_t*)xh)[i * 2 + 0] = pack_h2(v.x, v.y);
        ((uint32_t*)xh)[i * 2 + 1] = pack_h2(v.z, v.w);
    } else if (i < N4X + N4Q) {
        int j = i - N4X;
        float4 v = ((const float4*)wq)[j];
        float s = (j < C_ * C_ / 4) ? QSCALE : 1.0f;
        ((uint32_t*)wqh)[j * 2 + 0] = pack_h2(v.x * s, v.y * s);
        ((uint32_t*)wqh)[j * 2 + 1] = pack_h2(v.z * s, v.w * s);
    } else if (i < N4ALL) {
        int j = i - N4X - N4Q;
        float4 v = ((const float4*)wp)[j];
        ((uint32_t*)wph)[j * 2 + 0] = pack_h2(v.x, v.y);
        ((uint32_t*)wph)[j * 2 + 1] = pack_h2(v.z, v.w);
    }
}

// ---------------------------------------------------------------------------
// Prep: K fp16 [bh][M][D] + Vt fp16 [bh][D][M]; sources: ctx fp32 / qkv fp16
// ---------------------------------------------------------------------------
__global__ void prepkv_kernel(const __half* __restrict__ qkv, const float* __restrict__ ctx,
                              __half* __restrict__ kh, __half* __restrict__ vth) {
    __shared__ float sv[64][65];
    const int tid = threadIdx.x;
    const int kv0 = blockIdx.x * 64;
    const int bh  = blockIdx.y;
    const int b = bh >> 4, h = bh & 15;

#pragma unroll
    for (int it = 0; it < 4; it++) {
        int idx = tid + it * 256;
        int r  = idx >> 4;
        int dc = idx & 15;
        int kv = kv0 + r;
        float kx[4], vx[4];
        if (kv < NC_) {
            const float* base = ctx + (((size_t)(b * NC_ + kv)) * 2 + 0) * C_ + h * D_ + dc * 4;
            float4 kvec = *(const float4*)base;
            float4 vvec = *(const float4*)(base + C_);
            kx[0] = kvec.x; kx[1] = kvec.y; kx[2] = kvec.z; kx[3] = kvec.w;
            vx[0] = vvec.x; vx[1] = vvec.y; vx[2] = vvec.z; vx[3] = vvec.w;
        } else {
            const __half* base = qkv + (((size_t)(b * N_ + kv - NC_)) * 3 + 1) * C_ + h * D_ + dc * 4;
            __half2 k0 = *(const __half2*)base, k1 = *(const __half2*)(base + 2);
            __half2 w0 = *(const __half2*)(base + C_), w1 = *(const __half2*)(base + C_ + 2);
            kx[0] = __low2float(k0); kx[1] = __high2float(k0);
            kx[2] = __low2float(k1); kx[3] = __high2float(k1);
            vx[0] = __low2float(w0); vx[1] = __high2float(w0);
            vx[2] = __low2float(w1); vx[3] = __high2float(w1);
        }
        size_t o = (((size_t)bh) * M_ + kv) * D_ + dc * 4;
        *(uint32_t*)(kh + o)     = pack_h2(kx[0], kx[1]);
        *(uint32_t*)(kh + o + 2) = pack_h2(kx[2], kx[3]);
        sv[r][dc * 4 + 0] = vx[0]; sv[r][dc * 4 + 1] = vx[1];
        sv[r][dc * 4 + 2] = vx[2]; sv[r][dc * 4 + 3] = vx[3];
    }
    __syncthreads();

    {
        int d  = tid >> 2;
        int q4 = (tid & 3) * 16;
        size_t o = ((size_t)bh) * D_ * M_ + (size_t)d * M_ + kv0 + q4;
#pragma unroll
        for (int k2 = 0; k2 < 8; k2++) {
            *(uint32_t*)(vth + o + k2 * 2) =
                pack_h2(sv[q4 + k2 * 2][d], sv[q4 + k2 * 2 + 1][d]);
        }
    }
}

// ---------------------------------------------------------------------------
// mma.sync fp16 GEMM: 128x128 CTA, 4 warps (2x2) each 64x64, 128 threads,
// K-chunk 64, 3-stage cp.async, 2 CTAs/SM, separable swizzle.
// ---------------------------------------------------------------------------
#define GKC 64
#define TILE_B 16384
#define STAGE_BYTES (2 * TILE_B)           // A, B
#define GEMM_SMEM (3 * STAGE_BYTES + 1024)

__device__ __forceinline__ void load_tile128(const __half* __restrict__ src,
                                             int rbase, int K, int k0,
                                             uint32_t tb, int tid) {
#pragma unroll
    for (int i = 0; i < 8; i++) {
        int idx = tid + i * 128;
        int r = idx >> 3;
        int c = idx & 7;
        const void* g = src + (size_t)(rbase + r) * K + k0 + c * 8;
        cpa16(tb + sw128((uint32_t)(r * 128 + c * 16)), g);
    }
}

template <bool OUTHALF>
__global__ __launch_bounds__(128, 2) void gemm_mma(
    const __half* __restrict__ A, const __half* __restrict__ Bm,
    const float* __restrict__ bias,
    float* __restrict__ Cf, __half* __restrict__ Ch,
    int M, int N, int K)
{
    extern __shared__ char sm[];
    const uint32_t tiles = (smem_u32(sm) + 1023) & ~1023u;

    const int tid  = threadIdx.x;
    const int lane = tid & 31;
    const int wid  = tid >> 5;           // 0..3
    const int wm0  = (wid >> 1) * 64;
    const int wn0  = (wid & 1) * 64;
    const int bm = blockIdx.y * 128;
    const int bn = blockIdx.x * 128;

    const int lr = lane & 15;
    const int lc = (lane >> 4) << 4;
    const uint32_t xv = (uint32_t)((lr & 7) << 4);

    uint32_t arow[4], brow[4], colx[4];
#pragma unroll
    for (int mt = 0; mt < 4; mt++) arow[mt] = (uint32_t)((wm0 + mt * 16 + lr) * 128);
#pragma unroll
    for (int ng = 0; ng < 4; ng++) brow[ng] = (uint32_t)((wn0 + ng * 16 + lr) * 128) + TILE_B;
#pragma unroll
    for (int kk = 0; kk < 4; kk++) colx[kk] = ((uint32_t)(kk * 32 + lc)) ^ xv;

    float acc[4][8][4];
#pragma unroll
    for (int i = 0; i < 4; i++)
#pragma unroll
        for (int j = 0; j < 8; j++)
#pragma unroll
            for (int t = 0; t < 4; t++) acc[i][j][t] = 0.0f;

    const int NCH = K / GKC;

    {
        load_tile128(A,  bm, K, 0, tiles,          tid);
        load_tile128(Bm, bn, K, 0, tiles + TILE_B, tid);
        cpa_commit();
        load_tile128(A,  bm, K, GKC, tiles + STAGE_BYTES,          tid);
        load_tile128(Bm, bn, K, GKC, tiles + STAGE_BYTES + TILE_B, tid);
        cpa_commit();
    }

    int stage = 0;
    for (int k = 0; k < NCH; k++) {
        if (k + 1 < NCH) cpa_wait<1>(); else cpa_wait<0>();
        __syncthreads();
        if (k + 2 < NCH) {
            int ns = (stage + 2); if (ns >= 3) ns -= 3;
            uint32_t st = tiles + ns * STAGE_BYTES;
            const int k0 = (k + 2) * GKC;
            load_tile128(A,  bm, K, k0, st,          tid);
            load_tile128(Bm, bn, K, k0, st + TILE_B, tid);
            cpa_commit();
        }

        const uint32_t sb = tiles + stage * STAGE_BYTES;

#pragma unroll
        for (int kk = 0; kk < 4; kk++) {
            uint32_t af[4][4], bf[4][4];
#pragma unroll
            for (int mt = 0; mt < 4; mt++)
                ldsm_x4(af[mt], sb + arow[mt] + colx[kk]);
#pragma unroll
            for (int ng = 0; ng < 4; ng++)
                ldsm_x4(bf[ng], sb + brow[ng] + colx[kk]);
#pragma unroll
            for (int mt = 0; mt < 4; mt++)
#pragma unroll
                for (int nt = 0; nt < 8; nt++) {
                    const int ng = nt >> 1, s = nt & 1;
                    mma_fp16(acc[mt][nt], af[mt], bf[ng][s], bf[ng][2 + s]);
                }
        }
        if (++stage >= 3) stage = 0;
    }

    const int gq = lane >> 2;
    const int tg = lane & 3;
#pragma unroll
    for (int mt = 0; mt < 4; mt++) {
        const int row0 = bm + wm0 + mt * 16 + gq;
#pragma unroll
        for (int nt = 0; nt < 8; nt++) {
            const int col = bn + wn0 + nt * 8 + tg * 2;
            if (OUTHALF) {
                *(uint32_t*)(Ch + (size_t)row0 * N + col) =
                    pack_h2(acc[mt][nt][0], acc[mt][nt][1]);
                *(uint32_t*)(Ch + (size_t)(row0 + 8) * N + col) =
                    pack_h2(acc[mt][nt][2], acc[mt][nt][3]);
            } else {
                float b0v = bias[col], b1v = bias[col + 1];
                float2 v0 = make_float2(acc[mt][nt][0] + b0v, acc[mt][nt][1] + b1v);
                float2 v1 = make_float2(acc[mt][nt][2] + b0v, acc[mt][nt][3] + b1v);
                *(float2*)(Cf + (size_t)row0 * N + col)       = v0;
                *(float2*)(Cf + (size_t)(row0 + 8) * N + col) = v1;
            }
        }
    }
}

// ---------------------------------------------------------------------------
// Flash attention: 4 warps x 32 query rows (CTA = 128 q), 128 threads,
// 3-stage cp.async, base-2 softmax, separable swizzle. 2 CTAs/SM.
// smem: Q 16KB + 3 stages x 16KB = 64KB
// ---------------------------------------------------------------------------
#define AT_STAGE 16384
#define AT_SMEM (16384 + 3 * AT_STAGE + 1024)

__device__ __forceinline__ void at_load_kv(
    const __half* kh, const __half* vth, int kv0, uint32_t st, int tid)
{
#pragma unroll
    for (int i = 0; i < 4; i++) {
        int idx = tid + i * 128;
        int r = idx >> 3;        // 0..63
        int c = idx & 7;
        uint32_t so = sw128((uint32_t)(r * 128 + c * 16));
        cpa16(st + so,        kh  + (size_t)(kv0 + r) * D_ + c * 8);
        cpa16(st + 8192 + so, vth + (size_t)r * M_ + kv0 + c * 8);
    }
}

__global__ __launch_bounds__(128, 2) void attn_mma(
    const __half* __restrict__ qkv, const __half* __restrict__ Kh,
    const __half* __restrict__ Vth, __half* __restrict__ oh)
{
    extern __shared__ char sm[];
    const uint32_t base = (smem_u32(sm) + 1023) & ~1023u;
    const uint32_t sQ = base;
    const uint32_t sStage = base + 16384;

    const int tid  = threadIdx.x;
    const int lane = tid & 31;
    const int wid  = tid >> 5;           // 0..3
    const int qt = blockIdx.x;
    const int h  = blockIdx.y;
    const int b  = blockIdx.z;
    const int bh = b * H_ + h;

    const __half* qg  = qkv + ((size_t)(b * N_ + qt * 128) * 3) * C_ + h * D_;
    const __half* khg = Kh + (size_t)bh * M_ * D_;
    const __half* vhg = Vth + (size_t)bh * D_ * M_;

    // Q tile: 128 rows x 128B (row stride 3C in gmem)
#pragma unroll
    for (int i = 0; i < 8; i++) {
        int idx = tid + i * 128;
        int r = idx >> 3;        // 0..127
        int c = idx & 7;
        cpa16(sQ + sw128((uint32_t)(r * 128 + c * 16)),
              qg + (size_t)r * 3 * C_ + c * 8);
    }
    at_load_kv(khg, vhg, 0, sStage, tid);
    cpa_commit();
    at_load_kv(khg, vhg, 64, sStage + AT_STAGE, tid);
    cpa_commit();

    const int lr = lane & 15;
    const int lc = (lane >> 4) << 4;
    const int w32 = wid * 32;
    const uint32_t xv = (uint32_t)((lr & 7) << 4);

    uint32_t rowo[4], colx[4];
#pragma unroll
    for (int ng = 0; ng < 4; ng++) rowo[ng] = (uint32_t)((ng * 16 + lr) * 128);
#pragma unroll
    for (int kk = 0; kk < 4; kk++) colx[kk] = ((uint32_t)(kk * 32 + lc)) ^ xv;

    uint32_t qf[2][4][4];
    float O[2][8][4];
#pragma unroll
    for (int mf = 0; mf < 2; mf++)
#pragma unroll
        for (int nt = 0; nt < 8; nt++)
#pragma unroll
            for (int t = 0; t < 4; t++) O[mf][nt][t] = 0.0f;
    float mrow[2][2], lrow[2][2];
#pragma unroll
    for (int mf = 0; mf < 2; mf++) {
        mrow[mf][0] = -1e30f; mrow[mf][1] = -1e30f;
        lrow[mf][0] = 0.0f;   lrow[mf][1] = 0.0f;
    }

    int stage = 0;
    for (int kt = 0; kt < KVT; kt++) {
        if (kt + 1 < KVT) cpa_wait<1>(); else cpa_wait<0>();
        __syncthreads();
        if (kt + 2 < KVT) {
            int ns = stage + 2; if (ns >= 3) ns -= 3;
            at_load_kv(khg, vhg, (kt + 2) * 64, sStage + ns * AT_STAGE, tid);
            cpa_commit();
        }

        if (kt == 0) {
#pragma unroll
            for (int mf = 0; mf < 2; mf++) {
                const uint32_t qrow = sQ + (uint32_t)((w32 + mf * 16 + lr) * 128);
#pragma unroll
                for (int kk = 0; kk < 4; kk++)
                    ldsm_x4(qf[mf][kk], qrow + colx[kk]);
            }
        }

        const uint32_t tK = sStage + stage * AT_STAGE;
        const uint32_t tV = tK + 8192;

        // ---- S = Q . K^T (log2 domain) ----
        float S[2][8][4];
#pragma unroll
        for (int mf = 0; mf < 2; mf++)
#pragma unroll
            for (int nt = 0; nt < 8; nt++)
#pragma unroll
                for (int t = 0; t < 4; t++) S[mf][nt][t] = 0.0f;

#pragma unroll
        for (int kk = 0; kk < 4; kk++) {
            uint32_t bf[4][4];
#pragma unroll
            for (int ng = 0; ng < 4; ng++)
                ldsm_x4(bf[ng], tK + rowo[ng] + colx[kk]);
#pragma unroll
            for (int mf = 0; mf < 2; mf++)
#pragma unroll
                for (int ng = 0; ng < 4; ng++)
#pragma unroll
                    for (int s = 0; s < 2; s++)
                        mma_fp16(S[mf][ng * 2 + s], qf[mf][kk], bf[ng][s], bf[ng][2 + s]);
        }

        // ---- online softmax (base 2), per m-frag ----
        uint32_t ph[2][4][4];
#pragma unroll
        for (int mf = 0; mf < 2; mf++) {
            float mt0 = -1e30f, mt1 = -1e30f;
#pragma unroll
            for (int nt = 0; nt < 8; nt++) {
                mt0 = fmaxf(mt0, fmaxf(S[mf][nt][0], S[mf][nt][1]));
                mt1 = fmaxf(mt1, fmaxf(S[mf][nt][2], S[mf][nt][3]));
            }
            mt0 = fmaxf(mt0, __shfl_xor_sync(0xffffffffu, mt0, 1));
            mt0 = fmaxf(mt0, __shfl_xor_sync(0xffffffffu, mt0, 2));
            mt1 = fmaxf(mt1, __shfl_xor_sync(0xffffffffu, mt1, 1));
            mt1 = fmaxf(mt1, __shfl_xor_sync(0xffffffffu, mt1, 2));

            float mn0 = fmaxf(mrow[mf][0], mt0), mn1 = fmaxf(mrow[mf][1], mt1);
            float a0 = fexp2(mrow[mf][0] - mn0), a1 = fexp2(mrow[mf][1] - mn1);
            mrow[mf][0] = mn0; mrow[mf][1] = mn1;

            float rs0 = 0.0f, rs1 = 0.0f;
#pragma unroll
            for (int nt = 0; nt < 8; nt++) {
                S[mf][nt][0] = fexp2(S[mf][nt][0] - mn0);
                S[mf][nt][1] = fexp2(S[mf][nt][1] - mn0);
                S[mf][nt][2] = fexp2(S[mf][nt][2] - mn1);
                S[mf][nt][3] = fexp2(S[mf][nt][3] - mn1);
                rs0 += S[mf][nt][0] + S[mf][nt][1];
                rs1 += S[mf][nt][2] + S[mf][nt][3];
            }
            rs0 += __shfl_xor_sync(0xffffffffu, rs0, 1);
            rs0 += __shfl_xor_sync(0xffffffffu, rs0, 2);
            rs1 += __shfl_xor_sync(0xffffffffu, rs1, 1);
            rs1 += __shfl_xor_sync(0xffffffffu, rs1, 2);
            lrow[mf][0] = lrow[mf][0] * a0 + rs0;
            lrow[mf][1] = lrow[mf][1] * a1 + rs1;

#pragma unroll
            for (int nt = 0; nt < 8; nt++) {
                O[mf][nt][0] *= a0; O[mf][nt][1] *= a0;
                O[mf][nt][2] *= a1; O[mf][nt][3] *= a1;
            }

#pragma unroll
            for (int j = 0; j < 4; j++) {
                ph[mf][j][0] = pack_h2(S[mf][2 * j][0],     S[mf][2 * j][1]);
                ph[mf][j][1] = pack_h2(S[mf][2 * j][2],     S[mf][2 * j][3]);
                ph[mf][j][2] = pack_h2(S[mf][2 * j + 1][0], S[mf][2 * j + 1][1]);
                ph[mf][j][3] = pack_h2(S[mf][2 * j + 1][2], S[mf][2 * j + 1][3]);
            }
        }

        // ---- O += P . Vt^T ----
#pragma unroll
        for (int j = 0; j < 4; j++) {
            uint32_t vf[4][4];
#pragma unroll
            for (int ng = 0; ng < 4; ng++)
                ldsm_x4(vf[ng], tV + rowo[ng] + colx[j]);
#pragma unroll
            for (int mf = 0; mf < 2; mf++)
#pragma unroll
                for (int ng = 0; ng < 4; ng++)
#pragma unroll
                    for (int s = 0; s < 2; s++)
                        mma_fp16(O[mf][ng * 2 + s], ph[mf][j], vf[ng][s], vf[ng][2 + s]);
        }
        if (++stage >= 3) stage = 0;
    }

    // ---- epilogue ----
    const int g  = lane >> 2;
    const int tg = lane & 3;
#pragma unroll
    for (int mf = 0; mf < 2; mf++) {
        const float inv0 = 1.0f / lrow[mf][0], inv1 = 1.0f / lrow[mf][1];
        const int n0 = qt * 128 + w32 + mf * 16 + g;
#pragma unroll
        for (int nt = 0; nt < 8; nt++) {
            const int col = h * D_ + nt * 8 + tg * 2;
            *(uint32_t*)(oh + (size_t)(b * N_ + n0) * C_ + col) =
                pack_h2(O[mf][nt][0] * inv0, O[mf][nt][1] * inv0);
            *(uint32_t*)(oh + (size_t)(b * N_ + n0 + 8) * C_ + col) =
                pack_h2(O[mf][nt][2] * inv1, O[mf][nt][3] * inv1);
        }
    }
}

// ---------------------------------------------------------------------------
extern "C" void kernel_launch(void* const* d_in, const int* in_sizes, int n_in,
                              void* d_out, int out_size) {
    const float* x      = (const float*)d_in[0];
    const float* ctx    = (const float*)d_in[1];
    const float* w_qkv  = (const float*)d_in[2];
    const float* w_proj = (const float*)d_in[3];
    const float* b_proj = (const float*)d_in[4];
    float* out = (float*)d_out;

    void *p;
    cudaGetSymbolAddress(&p, g_qkvh);  __half* qkvh = (__half*)p;
    cudaGetSymbolAddress(&p, g_xh);    __half* xh   = (__half*)p;
    cudaGetSymbolAddress(&p, g_wqkv);  __half* wq   = (__half*)p;
    cudaGetSymbolAddress(&p, g_wproj); __half* wp   = (__half*)p;
    cudaGetSymbolAddress(&p, g_ah);    __half* ah   = (__half*)p;
    cudaGetSymbolAddress(&p, g_kh);    __half* kh   = (__half*)p;
    cudaGetSymbolAddress(&p, g_vth);   __half* vth  = (__half*)p;

    cudaFuncSetAttribute(gemm_mma<true>,  cudaFuncAttributeMaxDynamicSharedMemorySize, GEMM_SMEM);
    cudaFuncSetAttribute(gemm_mma<false>, cudaFuncAttributeMaxDynamicSharedMemorySize, GEMM_SMEM);
    cudaFuncSetAttribute(attn_mma,        cudaFuncAttributeMaxDynamicSharedMemorySize, AT_SMEM);

    // 0) convert inputs/weights to fp16 (Q-rows of w_qkv carry 0.125*log2e)
    decomp_all<<<(N4ALL + 255) / 256, 256>>>(x, w_qkv, w_proj, xh, wq, wp);

    // 1) QKV projection -> fp16 qkv
    {
        dim3 grid(3 * C_ / 128, B_ * N_ / 128);
        gemm_mma<true><<<grid, 128, GEMM_SMEM>>>(xh, wq, nullptr, nullptr, qkvh,
                                                 B_ * N_, 3 * C_, C_);
    }

    // 1.5) K gather + V transpose
    {
        dim3 grid(KVT, B_ * H_);
        prepkv_kernel<<<grid, 256>>>(qkvh, ctx, kh, vth);
    }

    // 2) Attention (base-2 softmax)
    {
        dim3 grid(N_ / 128, H_, B_);
        attn_mma<<<grid, 128, AT_SMEM>>>(qkvh, kh, vth, ah);
    }

    // 3) Output projection with bias -> fp32 out
    {
        dim3 grid(C_ / 128, B_ * N_ / 128);
        gemm_mma<false><<<grid, 128, GEMM_SMEM>>>(ah, wp, b_proj, out, nullptr,
                                                  B_ * N_, C_, C_);
    }
}